// round 5
// baseline (speedup 1.0000x reference)
#include <cuda_runtime.h>

// Problem constants
#define TT    256
#define BATCH 4096
#define H1    16
#define H2    64
#define BB    28          // batch tile per layer-2 block (14 packed f32x2 lanes)
#define L2_THREADS 192    // one thread per gate row (3*H2)

typedef unsigned long long u64;

// ---------------------------------------------------------------------------
// Scratch (static device globals — no allocation allowed)
// ---------------------------------------------------------------------------
__device__ float g_out1[(size_t)TT * BATCH * H1];   // layer-1 outputs [T][B][16]
__device__ float g_h[2 * (size_t)BATCH * H2];       // final hidden per dir [2][B][64]

// ---------------------------------------------------------------------------
// Packed f32x2 helpers (Blackwell, PTX ISA 8.6+, sm_100+)
// ---------------------------------------------------------------------------
#define FMA2(d, a, b, c) \
    asm("fma.rn.f32x2 %0, %1, %2, %3;" : "=l"(d) : "l"(a), "l"(b), "l"(c))
__device__ __forceinline__ u64 pack2(float x) {
    u64 d;
    asm("mov.b64 %0, {%1, %1};" : "=l"(d) : "f"(x));
    return d;
}

// ---------------------------------------------------------------------------
// Fast activations (fp32, MUFU-based)
// ---------------------------------------------------------------------------
__device__ __forceinline__ float sigf(float x) {
    return __fdividef(1.0f, 1.0f + __expf(-x));
}
__device__ __forceinline__ float tanhfast(float x) {
    return fmaf(2.0f, __fdividef(1.0f, 1.0f + __expf(-2.0f * x)), -1.0f);
}
__device__ __forceinline__ float gru_comb(float gr, float gz, float gn, float gx, float h) {
    float r = sigf(gr);
    float z = sigf(gz);
    float n = tanhfast(fmaf(r, gn, gx));
    return fmaf(z, h - n, n);   // (1-z)*n + z*h
}

// ---------------------------------------------------------------------------
// Layer 1: GRU(2 -> 16).  512 threads = 32 batch x 16 hidden; 128 blocks
// (one clean wave on 148 SMs).  Double-buffered h -> ONE barrier per step.
// ---------------------------------------------------------------------------
__global__ void __launch_bounds__(512)
gru1_kernel(const float* __restrict__ traj,
            const float* __restrict__ w_ih1,
            const float* __restrict__ w_hh1,
            const float* __restrict__ b_ih1,
            const float* __restrict__ b_hh1) {
    __shared__ float4 s_w4[16 * 16];    // [k][j] -> (w_r, w_z, w_n, 0)
    __shared__ float  s_h[2][32 * 17];  // double buffer, padded

    const int tid = threadIdx.x;
    const int bl  = tid >> 4;   // 0..31 batch-local
    const int j   = tid & 15;   // hidden unit
    const int gb  = blockIdx.x * 32 + bl;

    if (tid < 256) {
        int k = tid >> 4, jj = tid & 15;
        s_w4[k * 16 + jj] = make_float4(w_hh1[(jj)      * 16 + k],
                                        w_hh1[(16 + jj) * 16 + k],
                                        w_hh1[(32 + jj) * 16 + k],
                                        0.0f);
    }
    s_h[0][bl * 17 + j] = 0.0f;

    const float wxr0 = w_ih1[j * 2 + 0],        wxr1 = w_ih1[j * 2 + 1];
    const float wxz0 = w_ih1[(16 + j) * 2 + 0], wxz1 = w_ih1[(16 + j) * 2 + 1];
    const float wxn0 = w_ih1[(32 + j) * 2 + 0], wxn1 = w_ih1[(32 + j) * 2 + 1];
    const float br  = b_ih1[j]      + b_hh1[j];
    const float bz  = b_ih1[16 + j] + b_hh1[16 + j];
    const float bxn = b_ih1[32 + j];
    const float bhn = b_hh1[32 + j];
    __syncthreads();

    const float2* xp = (const float2*)(traj + (size_t)gb * TT * 2);
    float* op = g_out1 + (size_t)gb * 16 + j;

    float2 xv = xp[0];   // prefetch t=0
    int p = 0;
    for (int t = 0; t < TT; ++t) {
        float x0 = xv.x, x1 = xv.y;
        if (t + 1 < TT) xv = xp[t + 1];          // overlap LDG with compute

        float ar  = fmaf(wxr1, x1, fmaf(wxr0, x0, br));
        float az  = fmaf(wxz1, x1, fmaf(wxz0, x0, bz));
        float axn = fmaf(wxn1, x1, fmaf(wxn0, x0, bxn));
        float ahn = bhn;
        float hold = s_h[p][bl * 17 + j];
#pragma unroll
        for (int k = 0; k < 16; ++k) {
            float  h = s_h[p][bl * 17 + k];
            float4 w = s_w4[k * 16 + j];
            ar  = fmaf(w.x, h, ar);
            az  = fmaf(w.y, h, az);
            ahn = fmaf(w.z, h, ahn);
        }
        float r = sigf(ar);
        float z = sigf(az);
        float n = tanhfast(fmaf(r, ahn, axn));
        float hnew = fmaf(z, hold - n, n);
        s_h[1 - p][bl * 17 + j] = hnew;      // write OTHER buffer: no pre-sync needed
        op[(size_t)t * BATCH * 16] = hnew;
        p ^= 1;
        __syncthreads();                     // single barrier per step
    }
}

// ---------------------------------------------------------------------------
// Layer 2: bidirectional GRU(16 -> 64), last hidden only.
// grid = (147, 2).  192 threads; thread j owns gate-row j (weights in regs).
// Accumulators are packed f32x2 (fma.rn.f32x2) -> half the FFMA issue count.
// 2 barriers/step; next-step x tile prefetched into regs behind the mainloop.
// Dynamic smem (floats):
//   s_bih[192] s_bhh[192] s_g[192*28] s_gxn[64*28] s_hT[64*28] s_xT[16*28]
// ---------------------------------------------------------------------------
#define SM2_BIH 0
#define SM2_BHH 192
#define SM2_G   384
#define SM2_GXN 5760
#define SM2_HT  7552
#define SM2_XT  9344
#define SM2_TOTAL 9792   // 39168 bytes (< 48 KB, no attribute call needed)

__global__ void __launch_bounds__(L2_THREADS, 2)
gru2_kernel(const float* __restrict__ w_ihf, const float* __restrict__ w_hhf,
            const float* __restrict__ b_ihf, const float* __restrict__ b_hhf,
            const float* __restrict__ w_ihb, const float* __restrict__ w_hhb,
            const float* __restrict__ b_ihb, const float* __restrict__ b_hhb) {
    extern __shared__ float sm[];
    float* s_bih = sm + SM2_BIH;
    float* s_bhh = sm + SM2_BHH;
    float* s_g   = sm + SM2_G;
    float* s_gxn = sm + SM2_GXN;
    float* s_hT  = sm + SM2_HT;
    float* s_xT  = sm + SM2_XT;

    const int dir = blockIdx.y;
    const float* w_ih = dir ? w_ihb : w_ihf;
    const float* w_hh = dir ? w_hhb : w_hhf;
    const float* b_ih = dir ? b_ihb : b_ihf;
    const float* b_hh = dir ? b_hhb : b_hhf;

    const int j  = threadIdx.x;          // 0..191, owns gate row j
    const int b0 = blockIdx.x * BB;

    // Row-j weights into registers (rows contiguous, 16B-aligned).
    float wih_r[16];
    float whh_r[64];
    {
        const float4* pw = (const float4*)(w_ih + j * 16);
#pragma unroll
        for (int i = 0; i < 4; ++i) {
            float4 v = pw[i];
            wih_r[i * 4 + 0] = v.x; wih_r[i * 4 + 1] = v.y;
            wih_r[i * 4 + 2] = v.z; wih_r[i * 4 + 3] = v.w;
        }
        const float4* qw = (const float4*)(w_hh + j * 64);
#pragma unroll
        for (int i = 0; i < 16; ++i) {
            float4 v = qw[i];
            whh_r[i * 4 + 0] = v.x; whh_r[i * 4 + 1] = v.y;
            whh_r[i * 4 + 2] = v.z; whh_r[i * 4 + 3] = v.w;
        }
    }
    s_bih[j] = b_ih[j];
    s_bhh[j] = b_hh[j];
    for (int idx = j; idx < H2 * BB; idx += L2_THREADS) s_hT[idx] = 0.0f;
    __syncthreads();

    const float binit = (j < 128) ? (s_bih[j] + s_bhh[j]) : s_bih[j];
    const u64 binit2  = pack2(binit);
    const u64 bhh2    = pack2(s_bhh[j]);

    // ---- x-tile prefetch bookkeeping: 448 items over 192 threads (<=3 each)
    int    pf_sm[3];
    size_t pf_gm[3];
    int    pf_n = 0;
#pragma unroll
    for (int c = 0; c < 3; ++c) {
        int idx = j + c * L2_THREADS;
        if (idx < 16 * BB) {
            int bl = idx >> 4, k = idx & 15;
            int gb = b0 + bl; if (gb >= BATCH) gb = BATCH - 1;
            pf_sm[c] = k * BB + bl;
            pf_gm[c] = (size_t)gb * 16 + k;
            pf_n = c + 1;
        }
    }
    float pf[3];
    {
        const int t0 = dir ? (TT - 1) : 0;
#pragma unroll
        for (int c = 0; c < 3; ++c)
            if (c < pf_n) pf[c] = g_out1[(size_t)t0 * BATCH * 16 + pf_gm[c]];
    }

    for (int step = 0; step < TT; ++step) {
        // commit prefetched x tile for this step
#pragma unroll
        for (int c = 0; c < 3; ++c)
            if (c < pf_n) s_xT[pf_sm[c]] = pf[c];
        __syncthreads();   // x visible; also orders prev-step s_hT writes

        // kick off next step's x loads (hidden behind the mainloop)
        {
            int ns = step + 1 < TT ? step + 1 : step;
            int tn = dir ? (TT - 1 - ns) : ns;
#pragma unroll
            for (int c = 0; c < 3; ++c)
                if (c < pf_n) pf[c] = g_out1[(size_t)tn * BATCH * 16 + pf_gm[c]];
        }

        u64 acc[14];
#pragma unroll
        for (int i = 0; i < 14; ++i) acc[i] = binit2;

        // input projection: k = 0..15
#pragma unroll
        for (int k = 0; k < 16; ++k) {
            u64 w2 = pack2(wih_r[k]);
            const ulonglong2* xv = (const ulonglong2*)(s_xT + k * BB);
#pragma unroll
            for (int i = 0; i < 7; ++i) {
                ulonglong2 x = xv[i];   // LDS.128 broadcast
                FMA2(acc[2 * i],     w2, x.x, acc[2 * i]);
                FMA2(acc[2 * i + 1], w2, x.y, acc[2 * i + 1]);
            }
        }
        // n-gate keeps x-proj separate (needed inside tanh with r*hn)
        if (j >= 128) {
            ulonglong2* d = (ulonglong2*)(s_gxn + (j - 128) * BB);
#pragma unroll
            for (int i = 0; i < 7; ++i) {
                d[i] = make_ulonglong2(acc[2 * i], acc[2 * i + 1]);
                acc[2 * i] = bhh2; acc[2 * i + 1] = bhh2;
            }
        }
        // recurrent projection: k = 0..63
#pragma unroll
        for (int k = 0; k < 64; ++k) {
            u64 w2 = pack2(whh_r[k]);
            const ulonglong2* hv = (const ulonglong2*)(s_hT + k * BB);
#pragma unroll
            for (int i = 0; i < 7; ++i) {
                ulonglong2 h = hv[i];
                FMA2(acc[2 * i],     w2, h.x, acc[2 * i]);
                FMA2(acc[2 * i + 1], w2, h.y, acc[2 * i + 1]);
            }
        }
        {
            ulonglong2* d = (ulonglong2*)(s_g + j * BB);
#pragma unroll
            for (int i = 0; i < 7; ++i)
                d[i] = make_ulonglong2(acc[2 * i], acc[2 * i + 1]);
        }
        __syncthreads();

        // epilogue: 448 float4 items (64 hidden x 7 chunks) over 192 threads
        for (int item = j; item < 64 * 7; item += L2_THREADS) {
            int jj = item & 63;
            int i  = item >> 6;
            float4 vr = *(const float4*)(s_g   + jj         * BB + i * 4);
            float4 vz = *(const float4*)(s_g   + (64 + jj)  * BB + i * 4);
            float4 vn = *(const float4*)(s_g   + (128 + jj) * BB + i * 4);
            float4 vx = *(const float4*)(s_gxn + jj         * BB + i * 4);
            float4* hp = (float4*)(s_hT + jj * BB + i * 4);
            float4 vh = *hp;
            float4 o;
            o.x = gru_comb(vr.x, vz.x, vn.x, vx.x, vh.x);
            o.y = gru_comb(vr.y, vz.y, vn.y, vx.y, vh.y);
            o.z = gru_comb(vr.z, vz.z, vn.z, vx.z, vh.z);
            o.w = gru_comb(vr.w, vz.w, vn.w, vx.w, vh.w);
            *hp = o;
        }
        // no barrier here: next iteration's post-commit barrier orders s_hT
    }
    __syncthreads();

    // write final hidden state (coalesced over hidden index)
    for (int idx = j; idx < H2 * BB; idx += L2_THREADS) {
        int bl = idx >> 6, k = idx & 63;
        int gb = b0 + bl;
        if (gb < BATCH)
            g_h[(size_t)dir * BATCH * H2 + (size_t)gb * H2 + k] = s_hT[k * BB + bl];
    }
}

// ---------------------------------------------------------------------------
// MLP: out = ((h_fwd + h_bwd) @ W1^T + b1) @ W2^T + b2
// ---------------------------------------------------------------------------
__global__ void mlp_kernel(const float* __restrict__ W1, const float* __restrict__ b1,
                           const float* __restrict__ W2, const float* __restrict__ b2,
                           float* __restrict__ out) {
    __shared__ float s_w1t[64 * 32];
    __shared__ float s_w2t[32 * 8];
    __shared__ float s_b1[32];
    __shared__ float s_b2[8];
    __shared__ float s_m1[8 * 32];

    const int tid = threadIdx.x;
    for (int idx = tid; idx < 32 * 64; idx += 256) {
        int m = idx >> 6, k = idx & 63;
        s_w1t[k * 32 + m] = W1[idx];
    }
    if (tid < 8 * 32) { int o = tid >> 5, k = tid & 31; s_w2t[k * 8 + o] = W2[tid]; }
    if (tid < 32) s_b1[tid] = b1[tid];
    if (tid < 8)  s_b2[tid] = b2[tid];
    __syncthreads();

    const int bl = tid >> 5;
    const int m  = tid & 31;
    const int gb = blockIdx.x * 8 + bl;

    const float* hf = g_h + (size_t)gb * H2;
    const float* hb = g_h + (size_t)(BATCH + gb) * H2;

    float acc = s_b1[m];
#pragma unroll
    for (int k = 0; k < 64; ++k)
        acc = fmaf(s_w1t[k * 32 + m], hf[k] + hb[k], acc);
    s_m1[bl * 32 + m] = acc;
    __syncthreads();

    if (m < 8) {
        float a2 = s_b2[m];
#pragma unroll
        for (int k = 0; k < 32; ++k)
            a2 = fmaf(s_w2t[k * 8 + m], s_m1[bl * 32 + k], a2);
        out[(size_t)gb * 8 + m] = a2;
    }
}

// ---------------------------------------------------------------------------
// Launch (no attribute calls, no allocation, graph-capturable)
// ---------------------------------------------------------------------------
extern "C" void kernel_launch(void* const* d_in, const int* in_sizes, int n_in,
                              void* d_out, int out_size) {
    const float* traj   = (const float*)d_in[0];
    const float* w_ih1  = (const float*)d_in[1];
    const float* w_hh1  = (const float*)d_in[2];
    const float* b_ih1  = (const float*)d_in[3];
    const float* b_hh1  = (const float*)d_in[4];
    const float* w_ih2f = (const float*)d_in[5];
    const float* w_hh2f = (const float*)d_in[6];
    const float* b_ih2f = (const float*)d_in[7];
    const float* b_hh2f = (const float*)d_in[8];
    const float* w_ih2b = (const float*)d_in[9];
    const float* w_hh2b = (const float*)d_in[10];
    const float* b_ih2b = (const float*)d_in[11];
    const float* b_hh2b = (const float*)d_in[12];
    const float* W1     = (const float*)d_in[13];
    const float* b1     = (const float*)d_in[14];
    const float* W2     = (const float*)d_in[15];
    const float* b2     = (const float*)d_in[16];

    gru1_kernel<<<BATCH / 32, 512>>>(traj, w_ih1, w_hh1, b_ih1, b_hh1);

    dim3 grid2((BATCH + BB - 1) / BB, 2);               // (147, 2)
    gru2_kernel<<<grid2, L2_THREADS, SM2_TOTAL * sizeof(float)>>>(
        w_ih2f, w_hh2f, b_ih2f, b_hh2f,
        w_ih2b, w_hh2b, b_ih2b, b_hh2b);

    mlp_kernel<<<BATCH / 8, 256>>>(W1, b1, W2, b2, (float*)d_out);
}

// round 8
// speedup vs baseline: 1.8158x; 1.8158x over previous
#include <cuda_runtime.h>
#include <cuda_bf16.h>
#include <cstdint>

#define TT    256
#define BATCH 4096
#define H1    16
#define H2    64

// ---------------------------------------------------------------------------
// Scratch
// ---------------------------------------------------------------------------
__device__ float g_out1[(size_t)TT * BATCH * H1];   // layer-1 outputs [T][B][16]
__device__ float g_h[2 * (size_t)BATCH * H2];       // final hidden per dir

// ---------------------------------------------------------------------------
// MUFU activations (gru1 only)
// ---------------------------------------------------------------------------
__device__ __forceinline__ float sigf(float x) {
    return __fdividef(1.0f, 1.0f + __expf(-x));
}
__device__ __forceinline__ float tanhfast(float x) {
    return fmaf(2.0f, __fdividef(1.0f, 1.0f + __expf(-2.0f * x)), -1.0f);
}

// ---------------------------------------------------------------------------
// MUFU-free activations (gru2 epilogue): FMA/ALU only
// ---------------------------------------------------------------------------
__device__ __forceinline__ float sig_poly(float x) {
    float y = fminf(fmaxf(x * 1.4426950408889634f, -28.0f), 28.0f);
    int k = __float2int_rn(y);
    float f = y - (float)k;
    float p = 1.33335581e-3f;
    p = fmaf(p, f, 9.61812911e-3f);
    p = fmaf(p, f, 5.55041087e-2f);
    p = fmaf(p, f, 2.40226507e-1f);
    p = fmaf(p, f, 6.93147181e-1f);
    p = fmaf(p, f, 1.0f);
    float v = __int_as_float(__float_as_int(p) + (k << 23));   // 2^y
    float d = 1.0f + v;
    float r = __int_as_float(0x7EF311C3u - (unsigned)__float_as_int(d));
    r = r * (2.0f - d * r);
    r = r * (2.0f - d * r);
    r = r * (2.0f - d * r);
    return v * r;
}
__device__ __forceinline__ float tanh_poly(float x) {
    return fmaf(2.0f, sig_poly(x + x), -1.0f);
}

__device__ __forceinline__ uint32_t smem_u32(const void* p) {
    uint32_t a;
    asm("{ .reg .u64 t; cvta.to.shared.u64 t, %1; cvt.u32.u64 %0, t; }" : "=r"(a) : "l"(p));
    return a;
}

#define LDSM_X4(r0, r1, r2, r3, addr) \
    asm volatile("ldmatrix.sync.aligned.m8n8.x4.shared.b16 {%0,%1,%2,%3}, [%4];" \
        : "=r"(r0), "=r"(r1), "=r"(r2), "=r"(r3) : "r"(addr))

#define MMA_BF16(d, a0, a1, a2, a3, bb0, bb1) \
    asm volatile("mma.sync.aligned.m16n8k16.row.col.f32.bf16.bf16.f32 " \
        "{%0,%1,%2,%3}, {%4,%5,%6,%7}, {%8,%9}, {%0,%1,%2,%3};" \
        : "+f"((d)[0]), "+f"((d)[1]), "+f"((d)[2]), "+f"((d)[3]) \
        : "r"(a0), "r"(a1), "r"(a2), "r"(a3), "r"(bb0), "r"(bb1))

__device__ __forceinline__ void bf16_split(float v, unsigned short& hi, unsigned short& lo) {
    __nv_bfloat16 h = __float2bfloat16(v);
    float rem = v - __bfloat162float(h);
    __nv_bfloat16 l = __float2bfloat16(rem);
    hi = __bfloat16_as_ushort(h);
    lo = __bfloat16_as_ushort(l);
}

// ---------------------------------------------------------------------------
// Layer 2 (HMMA): A [64 rows x 248 cols bf16] double-buffered, B [192 x 248].
// A K layout: [0:64) h_hi | [64:128) h_lo | [128:192) h_hi
//           | [192:208) x_hi | [208:224) x_lo | [224:240) x_hi | pad
// B K layout (per gate row): [0:64) Whh_hi | [64:128) Whh_hi | [128:192) Whh_lo
//           | [192:208) Wih_hi | [208:224) Wih_hi | [224:240) Wih_lo
// so A.k*B.k sums to the 3-term split-bf16 product (hi*hi + lo*hi + hi*lo).
// ---------------------------------------------------------------------------
#define AROW  496
#define SM_A0 0
#define SM_A1 31744                 // 64*496
#define SM_B  63488
#define SM2_TOTAL (63488 + 192 * 496)   // 158720

__global__ void __launch_bounds__(256, 1)
gru2_kernel(const float* __restrict__ w_ihf, const float* __restrict__ w_hhf,
            const float* __restrict__ b_ihf, const float* __restrict__ b_hhf,
            const float* __restrict__ w_ihb, const float* __restrict__ w_hhb,
            const float* __restrict__ b_ihb, const float* __restrict__ b_hhb) {
    extern __shared__ char sm[];
    const uint32_t smb = smem_u32(sm);
    const int tid = threadIdx.x;
    const int wid = tid >> 5;
    const int lane = tid & 31;
    const int dir = blockIdx.y;
    const int b0 = blockIdx.x * 64;

    const float* w_ih = dir ? w_ihb : w_ihf;
    const float* w_hh = dir ? w_hhb : w_hhf;
    const float* b_ih = dir ? b_ihb : b_ihf;
    const float* b_hh = dir ? b_hhb : b_hhf;

    // ---- build B (static weights, split bf16) ----
    for (int idx = tid; idx < 192 * 64; idx += 256) {
        int g = idx >> 6, k = idx & 63;
        unsigned short hi, lo;
        bf16_split(w_hh[idx], hi, lo);
        unsigned short* row = (unsigned short*)(sm + SM_B + g * AROW);
        row[k] = hi; row[64 + k] = hi; row[128 + k] = lo;
    }
    for (int idx = tid; idx < 192 * 16; idx += 256) {
        int g = idx >> 4, k = idx & 15;
        unsigned short hi, lo;
        bf16_split(w_ih[idx], hi, lo);
        unsigned short* row = (unsigned short*)(sm + SM_B + g * AROW);
        // FIX (R8): must mirror A's x layout (x_hi|x_lo|x_hi) => W_hi|W_hi|W_lo
        row[192 + k] = hi; row[208 + k] = hi; row[224 + k] = lo;
    }
    for (int g = tid; g < 192; g += 256)   // zero pad cols [240:248)
        *(uint4*)(sm + SM_B + g * AROW + 480) = make_uint4(0, 0, 0, 0);

    // ---- zero A buf0 (h(0)=0) ----
    for (int idx = tid; idx < 64 * (AROW / 16); idx += 256)
        ((uint4*)(sm + SM_A0))[idx] = make_uint4(0, 0, 0, 0);

    // FIX (R8): order zeroing before x(t0) staging (they touch the same bytes
    // from different threads — was a data race).
    __syncthreads();

    const int xrow = tid >> 2;          // 0..63
    const int xq   = (tid & 3) * 4;     // 0,4,8,12
    {
        int t0 = dir ? (TT - 1) : 0;
        float4 xv = *(const float4*)(g_out1 + ((size_t)t0 * BATCH + b0 + xrow) * 16 + xq);
        float xs[4] = {xv.x, xv.y, xv.z, xv.w};
        unsigned short hi[4], lo[4];
#pragma unroll
        for (int e = 0; e < 4; ++e) bf16_split(xs[e], hi[e], lo[e]);
        uint2 HI = make_uint2(hi[0] | (hi[1] << 16), hi[2] | (hi[3] << 16));
        uint2 LO = make_uint2(lo[0] | (lo[1] << 16), lo[2] | (lo[3] << 16));
        char* ar = sm + SM_A0 + xrow * AROW;
        *(uint2*)(ar + 2 * (192 + xq)) = HI;
        *(uint2*)(ar + 2 * (208 + xq)) = LO;
        *(uint2*)(ar + 2 * (224 + xq)) = HI;
    }

    // ---- per-warp / per-lane constants ----
    const int mt = wid & 3;             // M-tile (16 rows)
    const int G0 = (wid >> 2) * 32;     // gate range [G0, G0+32)
    const int lrow = lane & 7;
    const int grp  = lane >> 3;
    const uint32_t aOff = (uint32_t)(mt * 16 + lrow + ((grp & 1) << 3)) * AROW
                        + (uint32_t)((grp >> 1) << 4);
    const uint32_t bOff = (uint32_t)(lrow + ((grp >> 1) << 3)) * AROW
                        + (uint32_t)((grp & 1) << 4);
    const uint32_t bBase = smb + SM_B + bOff;

    // biases -> registers
    const int cj = 2 * (lane & 3);
    float2 br[4], bz[4], bhn[4], bxn[4];
#pragma unroll
    for (int o = 0; o < 4; ++o) {
        int j = G0 + 8 * o + cj;
        br[o]  = make_float2(b_ih[j] + b_hh[j],           b_ih[j + 1] + b_hh[j + 1]);
        bz[o]  = make_float2(b_ih[64 + j] + b_hh[64 + j], b_ih[65 + j] + b_hh[65 + j]);
        bhn[o] = make_float2(b_hh[128 + j], b_hh[129 + j]);
        bxn[o] = make_float2(b_ih[128 + j], b_ih[129 + j]);
    }

    float h[16];
#pragma unroll
    for (int i = 0; i < 16; ++i) h[i] = 0.0f;

    __syncthreads();

    const int row0 = mt * 16 + (lane >> 2);
    const size_t xg_base = (size_t)(b0 + xrow) * 16 + xq;

    for (int step = 0; step < TT; ++step) {
        const uint32_t pa = smb + ((step & 1) ? SM_A1 : SM_A0);
        char* const   pn = sm + ((step & 1) ? SM_A0 : SM_A1);

        // prefetch x(t+1)
        float4 xv;
        const bool do_x = (step + 1 < TT);
        if (do_x) {
            int tn = dir ? (TT - 2 - step) : (step + 1);
            xv = *(const float4*)(g_out1 + (size_t)tn * BATCH * 16 + xg_base);
        }

        float d[16][4];
#pragma unroll
        for (int i = 0; i < 16; ++i) {
            d[i][0] = 0.f; d[i][1] = 0.f; d[i][2] = 0.f; d[i][3] = 0.f;
        }

        // ---- MMA phase ----
#pragma unroll
        for (int kc = 0; kc < 15; ++kc) {
            uint32_t a0, a1, a2, a3;
            LDSM_X4(a0, a1, a2, a3, pa + aOff + kc * 32);
            const uint32_t kb = (uint32_t)kc * 32;
            uint32_t q0, q1, q2, q3;
            // r section
            LDSM_X4(q0, q1, q2, q3, bBase + (uint32_t)G0 * AROW + kb);
            MMA_BF16(d[0], a0, a1, a2, a3, q0, q1);
            MMA_BF16(d[1], a0, a1, a2, a3, q2, q3);
            LDSM_X4(q0, q1, q2, q3, bBase + (uint32_t)(G0 + 16) * AROW + kb);
            MMA_BF16(d[2], a0, a1, a2, a3, q0, q1);
            MMA_BF16(d[3], a0, a1, a2, a3, q2, q3);
            // z section
            LDSM_X4(q0, q1, q2, q3, bBase + (uint32_t)(64 + G0) * AROW + kb);
            MMA_BF16(d[4], a0, a1, a2, a3, q0, q1);
            MMA_BF16(d[5], a0, a1, a2, a3, q2, q3);
            LDSM_X4(q0, q1, q2, q3, bBase + (uint32_t)(64 + G0 + 16) * AROW + kb);
            MMA_BF16(d[6], a0, a1, a2, a3, q0, q1);
            MMA_BF16(d[7], a0, a1, a2, a3, q2, q3);
            // n section: h-part (kc<12) -> hn accums; x-part (kc>=12) -> xn accums
            const int nA = (kc < 12) ? 8 : 12;
            LDSM_X4(q0, q1, q2, q3, bBase + (uint32_t)(128 + G0) * AROW + kb);
            MMA_BF16(d[nA],     a0, a1, a2, a3, q0, q1);
            MMA_BF16(d[nA + 1], a0, a1, a2, a3, q2, q3);
            LDSM_X4(q0, q1, q2, q3, bBase + (uint32_t)(128 + G0 + 16) * AROW + kb);
            MMA_BF16(d[nA + 2], a0, a1, a2, a3, q0, q1);
            MMA_BF16(d[nA + 3], a0, a1, a2, a3, q2, q3);
        }

        // ---- epilogue: gates + h update (no MUFU) ----
#pragma unroll
        for (int o = 0; o < 4; ++o) {
#pragma unroll
            for (int e = 0; e < 4; ++e) {
                float bR = (e & 1) ? br[o].y : br[o].x;
                float bZ = (e & 1) ? bz[o].y : bz[o].x;
                float bH = (e & 1) ? bhn[o].y : bhn[o].x;
                float bX = (e & 1) ? bxn[o].y : bxn[o].x;
                float rg = sig_poly(d[o][e] + bR);
                float zg = sig_poly(d[4 + o][e] + bZ);
                float nn = tanh_poly(fmaf(rg, d[8 + o][e] + bH, d[12 + o][e] + bX));
                const int hi = o * 4 + e;
                h[hi] = fmaf(zg, h[hi] - nn, nn);
            }
#pragma unroll
            for (int rsel = 0; rsel < 2; ++rsel) {
                const int e0 = rsel * 2;
                unsigned short h0, l0, h1, l1;
                bf16_split(h[o * 4 + e0],     h0, l0);
                bf16_split(h[o * 4 + e0 + 1], h1, l1);
                uint32_t HP = (uint32_t)h0 | ((uint32_t)h1 << 16);
                uint32_t LP = (uint32_t)l0 | ((uint32_t)l1 << 16);
                char* ar = pn + (row0 + rsel * 8) * AROW;
                const int j = G0 + 8 * o + cj;
                *(uint32_t*)(ar + 2 * j)         = HP;
                *(uint32_t*)(ar + 2 * (64 + j))  = LP;
                *(uint32_t*)(ar + 2 * (128 + j)) = HP;
            }
        }

        // stage x(t+1) into next buffer
        if (do_x) {
            float xs[4] = {xv.x, xv.y, xv.z, xv.w};
            unsigned short hi[4], lo[4];
#pragma unroll
            for (int e = 0; e < 4; ++e) bf16_split(xs[e], hi[e], lo[e]);
            uint2 HI = make_uint2(hi[0] | (hi[1] << 16), hi[2] | (hi[3] << 16));
            uint2 LO = make_uint2(lo[0] | (lo[1] << 16), lo[2] | (lo[3] << 16));
            char* ar = pn + xrow * AROW;
            *(uint2*)(ar + 2 * (192 + xq)) = HI;
            *(uint2*)(ar + 2 * (208 + xq)) = LO;
            *(uint2*)(ar + 2 * (224 + xq)) = HI;
        }
        __syncthreads();
    }

    // final hidden -> gmem
#pragma unroll
    for (int o = 0; o < 4; ++o) {
#pragma unroll
        for (int rsel = 0; rsel < 2; ++rsel) {
            const int j = G0 + 8 * o + cj;
            float* hp = g_h + ((size_t)dir * BATCH + b0 + row0 + rsel * 8) * H2 + j;
            *(float2*)hp = make_float2(h[o * 4 + rsel * 2], h[o * 4 + rsel * 2 + 1]);
        }
    }
}

// ---------------------------------------------------------------------------
// Layer 1: GRU(2 -> 16), unchanged.
// ---------------------------------------------------------------------------
__global__ void __launch_bounds__(512)
gru1_kernel(const float* __restrict__ traj,
            const float* __restrict__ w_ih1,
            const float* __restrict__ w_hh1,
            const float* __restrict__ b_ih1,
            const float* __restrict__ b_hh1) {
    __shared__ float4 s_w4[16 * 16];
    __shared__ float  s_h[2][32 * 17];

    const int tid = threadIdx.x;
    const int bl  = tid >> 4;
    const int j   = tid & 15;
    const int gb  = blockIdx.x * 32 + bl;

    if (tid < 256) {
        int k = tid >> 4, jj = tid & 15;
        s_w4[k * 16 + jj] = make_float4(w_hh1[(jj)      * 16 + k],
                                        w_hh1[(16 + jj) * 16 + k],
                                        w_hh1[(32 + jj) * 16 + k],
                                        0.0f);
    }
    s_h[0][bl * 17 + j] = 0.0f;

    const float wxr0 = w_ih1[j * 2 + 0],        wxr1 = w_ih1[j * 2 + 1];
    const float wxz0 = w_ih1[(16 + j) * 2 + 0], wxz1 = w_ih1[(16 + j) * 2 + 1];
    const float wxn0 = w_ih1[(32 + j) * 2 + 0], wxn1 = w_ih1[(32 + j) * 2 + 1];
    const float br  = b_ih1[j]      + b_hh1[j];
    const float bz  = b_ih1[16 + j] + b_hh1[16 + j];
    const float bxn = b_ih1[32 + j];
    const float bhn = b_hh1[32 + j];
    __syncthreads();

    const float2* xp = (const float2*)(traj + (size_t)gb * TT * 2);
    float* op = g_out1 + (size_t)gb * 16 + j;

    float2 xv = xp[0];
    int p = 0;
    for (int t = 0; t < TT; ++t) {
        float x0 = xv.x, x1 = xv.y;
        if (t + 1 < TT) xv = xp[t + 1];

        float ar  = fmaf(wxr1, x1, fmaf(wxr0, x0, br));
        float az  = fmaf(wxz1, x1, fmaf(wxz0, x0, bz));
        float axn = fmaf(wxn1, x1, fmaf(wxn0, x0, bxn));
        float ahn = bhn;
        float hold = s_h[p][bl * 17 + j];
#pragma unroll
        for (int k = 0; k < 16; ++k) {
            float  hh = s_h[p][bl * 17 + k];
            float4 w = s_w4[k * 16 + j];
            ar  = fmaf(w.x, hh, ar);
            az  = fmaf(w.y, hh, az);
            ahn = fmaf(w.z, hh, ahn);
        }
        float r = sigf(ar);
        float z = sigf(az);
        float n = tanhfast(fmaf(r, ahn, axn));
        float hnew = fmaf(z, hold - n, n);
        s_h[1 - p][bl * 17 + j] = hnew;
        op[(size_t)t * BATCH * 16] = hnew;
        p ^= 1;
        __syncthreads();
    }
}

// ---------------------------------------------------------------------------
// MLP
// ---------------------------------------------------------------------------
__global__ void mlp_kernel(const float* __restrict__ W1, const float* __restrict__ b1,
                           const float* __restrict__ W2, const float* __restrict__ b2,
                           float* __restrict__ out) {
    __shared__ float s_w1t[64 * 32];
    __shared__ float s_w2t[32 * 8];
    __shared__ float s_b1[32];
    __shared__ float s_b2[8];
    __shared__ float s_m1[8 * 32];

    const int tid = threadIdx.x;
    for (int idx = tid; idx < 32 * 64; idx += 256) {
        int mm = idx >> 6, k = idx & 63;
        s_w1t[k * 32 + mm] = W1[idx];
    }
    if (tid < 8 * 32) { int o = tid >> 5, k = tid & 31; s_w2t[k * 8 + o] = W2[tid]; }
    if (tid < 32) s_b1[tid] = b1[tid];
    if (tid < 8)  s_b2[tid] = b2[tid];
    __syncthreads();

    const int bl = tid >> 5;
    const int mm = tid & 31;
    const int gb = blockIdx.x * 8 + bl;

    const float* hf = g_h + (size_t)gb * H2;
    const float* hb = g_h + (size_t)(BATCH + gb) * H2;

    float acc = s_b1[mm];
#pragma unroll
    for (int k = 0; k < 64; ++k)
        acc = fmaf(s_w1t[k * 32 + mm], hf[k] + hb[k], acc);
    s_m1[bl * 32 + mm] = acc;
    __syncthreads();

    if (mm < 8) {
        float a2 = s_b2[mm];
#pragma unroll
        for (int k = 0; k < 32; ++k)
            a2 = fmaf(s_w2t[k * 8 + mm], s_m1[bl * 32 + k], a2);
        out[(size_t)gb * 8 + mm] = a2;
    }
}

// ---------------------------------------------------------------------------
// Launch
// ---------------------------------------------------------------------------
extern "C" void kernel_launch(void* const* d_in, const int* in_sizes, int n_in,
                              void* d_out, int out_size) {
    const float* traj   = (const float*)d_in[0];
    const float* w_ih1  = (const float*)d_in[1];
    const float* w_hh1  = (const float*)d_in[2];
    const float* b_ih1  = (const float*)d_in[3];
    const float* b_hh1  = (const float*)d_in[4];
    const float* w_ih2f = (const float*)d_in[5];
    const float* w_hh2f = (const float*)d_in[6];
    const float* b_ih2f = (const float*)d_in[7];
    const float* b_hh2f = (const float*)d_in[8];
    const float* w_ih2b = (const float*)d_in[9];
    const float* w_hh2b = (const float*)d_in[10];
    const float* b_ih2b = (const float*)d_in[11];
    const float* b_hh2b = (const float*)d_in[12];
    const float* W1     = (const float*)d_in[13];
    const float* b1     = (const float*)d_in[14];
    const float* W2     = (const float*)d_in[15];
    const float* b2     = (const float*)d_in[16];

    cudaFuncSetAttribute(gru2_kernel,
                         cudaFuncAttributeMaxDynamicSharedMemorySize, SM2_TOTAL);

    gru1_kernel<<<BATCH / 32, 512>>>(traj, w_ih1, w_hh1, b_ih1, b_hh1);

    dim3 grid2(BATCH / 64, 2);   // (64, 2)
    gru2_kernel<<<grid2, 256, SM2_TOTAL>>>(w_ih2f, w_hh2f, b_ih2f, b_hh2f,
                                           w_ih2b, w_hh2b, b_ih2b, b_hh2b);

    mlp_kernel<<<BATCH / 8, 256>>>(W1, b1, W2, b2, (float*)d_out);
}

// round 9
// speedup vs baseline: 2.2129x; 1.2187x over previous
#include <cuda_runtime.h>
#include <cuda_bf16.h>
#include <cstdint>

#define TT    256
#define BATCH 4096
#define H1    16
#define H2    64

// ---------------------------------------------------------------------------
// Scratch
// ---------------------------------------------------------------------------
__device__ float g_out1[(size_t)TT * BATCH * H1];   // layer-1 outputs [T][B][16]
__device__ float g_h[2 * (size_t)BATCH * H2];       // final hidden per dir

// ---------------------------------------------------------------------------
// MUFU-free activations: FMA/ALU only
// ---------------------------------------------------------------------------
__device__ __forceinline__ float sig_poly(float x) {
    float y = fminf(fmaxf(x * 1.4426950408889634f, -28.0f), 28.0f);
    int k = __float2int_rn(y);
    float f = y - (float)k;
    float p = 1.33335581e-3f;
    p = fmaf(p, f, 9.61812911e-3f);
    p = fmaf(p, f, 5.55041087e-2f);
    p = fmaf(p, f, 2.40226507e-1f);
    p = fmaf(p, f, 6.93147181e-1f);
    p = fmaf(p, f, 1.0f);
    float v = __int_as_float(__float_as_int(p) + (k << 23));   // 2^y
    float d = 1.0f + v;
    float r = __int_as_float(0x7EF311C3u - (unsigned)__float_as_int(d));
    r = r * (2.0f - d * r);
    r = r * (2.0f - d * r);
    r = r * (2.0f - d * r);
    return v * r;
}
__device__ __forceinline__ float tanh_poly(float x) {
    return fmaf(2.0f, sig_poly(x + x), -1.0f);
}

__device__ __forceinline__ uint32_t smem_u32(const void* p) {
    uint32_t a;
    asm("{ .reg .u64 t; cvta.to.shared.u64 t, %1; cvt.u32.u64 %0, t; }" : "=r"(a) : "l"(p));
    return a;
}

#define LDSM_X4(r0, r1, r2, r3, addr) \
    asm volatile("ldmatrix.sync.aligned.m8n8.x4.shared.b16 {%0,%1,%2,%3}, [%4];" \
        : "=r"(r0), "=r"(r1), "=r"(r2), "=r"(r3) : "r"(addr))

#define MMA_BF16(d, a0, a1, a2, a3, bb0, bb1) \
    asm volatile("mma.sync.aligned.m16n8k16.row.col.f32.bf16.bf16.f32 " \
        "{%0,%1,%2,%3}, {%4,%5,%6,%7}, {%8,%9}, {%0,%1,%2,%3};" \
        : "+f"((d)[0]), "+f"((d)[1]), "+f"((d)[2]), "+f"((d)[3]) \
        : "r"(a0), "r"(a1), "r"(a2), "r"(a3), "r"(bb0), "r"(bb1))

__device__ __forceinline__ void bf16_split(float v, unsigned short& hi, unsigned short& lo) {
    __nv_bfloat16 h = __float2bfloat16(v);
    float rem = v - __bfloat162float(h);
    __nv_bfloat16 l = __float2bfloat16(rem);
    hi = __bfloat16_as_ushort(h);
    lo = __bfloat16_as_ushort(l);
}

// ---------------------------------------------------------------------------
// Layer 2 (HMMA, dedup K): A [32 rows x 160 cols bf16] double-buffered,
// B [192 x 160].  Col map (bf16 index):
//   A: [0:64) h_hi | [64:128) h_lo | [128:144) x_hi | [144:160) x_lo
//   B: [0:64) Whh_hi | [64:128) Whh_lo | [128:144) Wih_hi | [144:160) Wih_lo
// 3-term split products realized by section pairing in the MMA loop:
//   h_hi*Whh_hi + h_lo*Whh_hi + h_hi*Whh_lo  (same for x / Wih)
// M=32/CTA, 4 warps, grid (128,2) -> 2 CTAs/SM phase overlap.
// ---------------------------------------------------------------------------
#define AROW   336
#define SM_A0  0
#define SM_A1  10752                 // 32*336
#define SM_B   21504
#define SM2_TOTAL (21504 + 192 * 336)    // 86016

__global__ void __launch_bounds__(128, 2)
gru2_kernel(const float* __restrict__ w_ihf, const float* __restrict__ w_hhf,
            const float* __restrict__ b_ihf, const float* __restrict__ b_hhf,
            const float* __restrict__ w_ihb, const float* __restrict__ w_hhb,
            const float* __restrict__ b_ihb, const float* __restrict__ b_hhb) {
    extern __shared__ char sm[];
    const uint32_t smb = smem_u32(sm);
    const int tid = threadIdx.x;
    const int wid = tid >> 5;
    const int lane = tid & 31;
    const int dir = blockIdx.y;
    const int b0 = blockIdx.x * 32;

    const float* w_ih = dir ? w_ihb : w_ihf;
    const float* w_hh = dir ? w_hhb : w_hhf;
    const float* b_ih = dir ? b_ihb : b_ihf;
    const float* b_hh = dir ? b_hhb : b_hhf;

    // ---- build B ----
    for (int idx = tid; idx < 192 * 64; idx += 128) {
        int g = idx >> 6, k = idx & 63;
        unsigned short hi, lo;
        bf16_split(w_hh[idx], hi, lo);
        unsigned short* row = (unsigned short*)(sm + SM_B + g * AROW);
        row[k] = hi; row[64 + k] = lo;
    }
    for (int idx = tid; idx < 192 * 16; idx += 128) {
        int g = idx >> 4, k = idx & 15;
        unsigned short hi, lo;
        bf16_split(w_ih[idx], hi, lo);
        unsigned short* row = (unsigned short*)(sm + SM_B + g * AROW);
        row[128 + k] = hi; row[144 + k] = lo;
    }
    for (int g = tid; g < 192; g += 128)   // zero tail pad [320:336)
        *(uint4*)(sm + SM_B + g * AROW + 320) = make_uint4(0, 0, 0, 0);

    // ---- zero A buf0 (h(0)=0) ----
    for (int idx = tid; idx < 32 * (AROW / 16); idx += 128)
        ((uint4*)(sm + SM_A0))[idx] = make_uint4(0, 0, 0, 0);
    __syncthreads();

    // ---- stage x(t0): 128 threads = 32 rows x 4 cols each ----
    const int xrow = tid >> 2;          // 0..31
    const int xq   = (tid & 3) * 4;     // 0,4,8,12
    {
        int t0 = dir ? (TT - 1) : 0;
        float4 xv = *(const float4*)(g_out1 + ((size_t)t0 * BATCH + b0 + xrow) * 16 + xq);
        float xs[4] = {xv.x, xv.y, xv.z, xv.w};
        unsigned short hi[4], lo[4];
#pragma unroll
        for (int e = 0; e < 4; ++e) bf16_split(xs[e], hi[e], lo[e]);
        uint2 HI = make_uint2(hi[0] | (hi[1] << 16), hi[2] | (hi[3] << 16));
        uint2 LO = make_uint2(lo[0] | (lo[1] << 16), lo[2] | (lo[3] << 16));
        char* ar = sm + SM_A0 + xrow * AROW;
        *(uint2*)(ar + 256 + 2 * xq) = HI;   // x_hi at col 128
        *(uint2*)(ar + 288 + 2 * xq) = LO;   // x_lo at col 144
    }

    // ---- per-warp / per-lane constants ----
    const int mt = wid & 1;             // M-tile (16 rows): rows mt*16..
    const int G0 = (wid >> 1) * 32;     // gate range [G0, G0+32)
    const int lrow = lane & 7;
    const int grp  = lane >> 3;
    const uint32_t aRowOff = (uint32_t)(mt * 16 + lrow + ((grp & 1) << 3)) * AROW
                           + (uint32_t)((grp >> 1) << 4);
    const uint32_t bOff = (uint32_t)(lrow + ((grp >> 1) << 3)) * AROW
                        + (uint32_t)((grp & 1) << 4);
    const uint32_t bBase = smb + SM_B + bOff;

    // biases -> registers
    const int cj = 2 * (lane & 3);
    float2 br[4], bz[4], bhn[4], bxn[4];
#pragma unroll
    for (int o = 0; o < 4; ++o) {
        int j = G0 + 8 * o + cj;
        br[o]  = make_float2(b_ih[j] + b_hh[j],           b_ih[j + 1] + b_hh[j + 1]);
        bz[o]  = make_float2(b_ih[64 + j] + b_hh[64 + j], b_ih[65 + j] + b_hh[65 + j]);
        bhn[o] = make_float2(b_hh[128 + j], b_hh[129 + j]);
        bxn[o] = make_float2(b_ih[128 + j], b_ih[129 + j]);
    }

    float h[16];
#pragma unroll
    for (int i = 0; i < 16; ++i) h[i] = 0.0f;

    __syncthreads();

    const int row0 = mt * 16 + (lane >> 2);
    const size_t xg_base = (size_t)(b0 + xrow) * 16 + xq;

    for (int step = 0; step < TT; ++step) {
        const uint32_t pa = smb + ((step & 1) ? SM_A1 : SM_A0);
        char* const   pn = sm + ((step & 1) ? SM_A0 : SM_A1);

        // prefetch x(t+1)
        float4 xv;
        const bool do_x = (step + 1 < TT);
        if (do_x) {
            int tn = dir ? (TT - 2 - step) : (step + 1);
            xv = *(const float4*)(g_out1 + (size_t)tn * BATCH * 16 + xg_base);
        }

        // ---- load all A fragments for this step (10 LDSM) ----
        uint32_t ah[4][4], al[4][4], axh[4], axl[4];
#pragma unroll
        for (int kc = 0; kc < 4; ++kc)
            LDSM_X4(ah[kc][0], ah[kc][1], ah[kc][2], ah[kc][3], pa + aRowOff + kc * 32);
#pragma unroll
        for (int kc = 0; kc < 4; ++kc)
            LDSM_X4(al[kc][0], al[kc][1], al[kc][2], al[kc][3], pa + aRowOff + 128 + kc * 32);
        LDSM_X4(axh[0], axh[1], axh[2], axh[3], pa + aRowOff + 256);
        LDSM_X4(axl[0], axl[1], axl[2], axl[3], pa + aRowOff + 288);

        float d[16][4];
#pragma unroll
        for (int i = 0; i < 16; ++i) {
            d[i][0] = 0.f; d[i][1] = 0.f; d[i][2] = 0.f; d[i][3] = 0.f;
        }

        // ---- MMA phase: 6 gate blocks x (h: 4 kc, x: 1) ----
#pragma unroll
        for (int sec = 0; sec < 3; ++sec) {
#pragma unroll
            for (int nb = 0; nb < 2; ++nb) {
                const uint32_t rowb = bBase + (uint32_t)(sec * 64 + G0 + nb * 16) * AROW;
                const int iH = (sec < 2 ? sec * 4 : 8) + nb * 2;   // r/z/hn accums
                const int iX = (sec < 2 ? sec * 4 : 12) + nb * 2;  // r/z/xn accums
                uint32_t q0, q1, q2, q3;
#pragma unroll
                for (int kc = 0; kc < 4; ++kc) {
                    // Whh_hi block: pairs with h_hi AND h_lo
                    LDSM_X4(q0, q1, q2, q3, rowb + kc * 32);
                    MMA_BF16(d[iH],     ah[kc][0], ah[kc][1], ah[kc][2], ah[kc][3], q0, q1);
                    MMA_BF16(d[iH + 1], ah[kc][0], ah[kc][1], ah[kc][2], ah[kc][3], q2, q3);
                    MMA_BF16(d[iH],     al[kc][0], al[kc][1], al[kc][2], al[kc][3], q0, q1);
                    MMA_BF16(d[iH + 1], al[kc][0], al[kc][1], al[kc][2], al[kc][3], q2, q3);
                    // Whh_lo block: pairs with h_hi only
                    LDSM_X4(q0, q1, q2, q3, rowb + 128 + kc * 32);
                    MMA_BF16(d[iH],     ah[kc][0], ah[kc][1], ah[kc][2], ah[kc][3], q0, q1);
                    MMA_BF16(d[iH + 1], ah[kc][0], ah[kc][1], ah[kc][2], ah[kc][3], q2, q3);
                }
                // Wih_hi: pairs with x_hi and x_lo
                LDSM_X4(q0, q1, q2, q3, rowb + 256);
                MMA_BF16(d[iX],     axh[0], axh[1], axh[2], axh[3], q0, q1);
                MMA_BF16(d[iX + 1], axh[0], axh[1], axh[2], axh[3], q2, q3);
                MMA_BF16(d[iX],     axl[0], axl[1], axl[2], axl[3], q0, q1);
                MMA_BF16(d[iX + 1], axl[0], axl[1], axl[2], axl[3], q2, q3);
                // Wih_lo: pairs with x_hi
                LDSM_X4(q0, q1, q2, q3, rowb + 288);
                MMA_BF16(d[iX],     axh[0], axh[1], axh[2], axh[3], q0, q1);
                MMA_BF16(d[iX + 1], axh[0], axh[1], axh[2], axh[3], q2, q3);
            }
        }

        __syncthreads();   // everyone done READING A(cur) & computing; safe to overwrite next buf... (pn is the other buffer; this barrier orders pn writes vs next step's reads)

        // ---- epilogue: gates + h update (FMA/ALU only) ----
#pragma unroll
        for (int o = 0; o < 4; ++o) {
#pragma unroll
            for (int e = 0; e < 4; ++e) {
                float bR = (e & 1) ? br[o].y : br[o].x;
                float bZ = (e & 1) ? bz[o].y : bz[o].x;
                float bH = (e & 1) ? bhn[o].y : bhn[o].x;
                float bX = (e & 1) ? bxn[o].y : bxn[o].x;
                float rg = sig_poly(d[o][e] + bR);
                float zg = sig_poly(d[4 + o][e] + bZ);
                float nn = tanh_poly(fmaf(rg, d[8 + o][e] + bH, d[12 + o][e] + bX));
                const int hi = o * 4 + e;
                h[hi] = fmaf(zg, h[hi] - nn, nn);
            }
#pragma unroll
            for (int rsel = 0; rsel < 2; ++rsel) {
                const int e0 = rsel * 2;
                unsigned short h0, l0, h1, l1;
                bf16_split(h[o * 4 + e0],     h0, l0);
                bf16_split(h[o * 4 + e0 + 1], h1, l1);
                uint32_t HP = (uint32_t)h0 | ((uint32_t)h1 << 16);
                uint32_t LP = (uint32_t)l0 | ((uint32_t)l1 << 16);
                char* ar = pn + (row0 + rsel * 8) * AROW;
                const int j = G0 + 8 * o + cj;
                *(uint32_t*)(ar + 2 * j)         = HP;   // h_hi
                *(uint32_t*)(ar + 128 + 2 * j)   = LP;   // h_lo (col 64)
            }
        }

        // stage x(t+1) into next buffer
        if (do_x) {
            float xs[4] = {xv.x, xv.y, xv.z, xv.w};
            unsigned short hi[4], lo[4];
#pragma unroll
            for (int e = 0; e < 4; ++e) bf16_split(xs[e], hi[e], lo[e]);
            uint2 HI = make_uint2(hi[0] | (hi[1] << 16), hi[2] | (hi[3] << 16));
            uint2 LO = make_uint2(lo[0] | (lo[1] << 16), lo[2] | (lo[3] << 16));
            char* ar = pn + xrow * AROW;
            *(uint2*)(ar + 256 + 2 * xq) = HI;
            *(uint2*)(ar + 288 + 2 * xq) = LO;
        }
        __syncthreads();   // A(next) complete before next step's LDSMs
    }

    // final hidden -> gmem
#pragma unroll
    for (int o = 0; o < 4; ++o) {
#pragma unroll
        for (int rsel = 0; rsel < 2; ++rsel) {
            const int j = G0 + 8 * o + cj;
            float* hp = g_h + ((size_t)dir * BATCH + b0 + row0 + rsel * 8) * H2 + j;
            *(float2*)hp = make_float2(h[o * 4 + rsel * 2], h[o * 4 + rsel * 2 + 1]);
        }
    }
}

// ---------------------------------------------------------------------------
// Layer 1: GRU(2 -> 16), barrier-free warp-shuffle version.
// 2 batch elements per warp (lanes 0-15 / 16-31); h lives in lanes;
// recurrent broadcast via shfl; FMA-only poly activations; zero barriers.
// ---------------------------------------------------------------------------
__global__ void __launch_bounds__(256)
gru1_kernel(const float* __restrict__ traj,
            const float* __restrict__ w_ih1,
            const float* __restrict__ w_hh1,
            const float* __restrict__ b_ih1,
            const float* __restrict__ b_hh1) {
    const int tid  = threadIdx.x;
    const int wid  = tid >> 5;
    const int lane = tid & 31;
    const int half = lane >> 4;          // which batch element in warp
    const int j    = lane & 15;          // hidden unit
    const int el   = (blockIdx.x * 8 + wid) * 2 + half;

    // recurrent weights row j (3 gates x 16) -> registers
    float whr[16], whz[16], whn[16];
#pragma unroll
    for (int k = 0; k < 16; ++k) {
        whr[k] = w_hh1[(j)      * 16 + k];
        whz[k] = w_hh1[(16 + j) * 16 + k];
        whn[k] = w_hh1[(32 + j) * 16 + k];
    }
    const float wxr0 = w_ih1[j * 2 + 0],        wxr1 = w_ih1[j * 2 + 1];
    const float wxz0 = w_ih1[(16 + j) * 2 + 0], wxz1 = w_ih1[(16 + j) * 2 + 1];
    const float wxn0 = w_ih1[(32 + j) * 2 + 0], wxn1 = w_ih1[(32 + j) * 2 + 1];
    const float br  = b_ih1[j]      + b_hh1[j];
    const float bz  = b_ih1[16 + j] + b_hh1[16 + j];
    const float bxn = b_ih1[32 + j];
    const float bhn = b_hh1[32 + j];

    const float2* xp = (const float2*)(traj + (size_t)el * TT * 2);
    float* op = g_out1 + (size_t)el * 16 + j;
    const int sbase = half << 4;         // shfl source base for this half

    float h = 0.0f;
    float2 xv = xp[0];
    for (int t = 0; t < TT; ++t) {
        float x0 = xv.x, x1 = xv.y;
        if (t + 1 < TT) xv = xp[t + 1];

        float ar  = fmaf(wxr1, x1, fmaf(wxr0, x0, br));
        float az  = fmaf(wxz1, x1, fmaf(wxz0, x0, bz));
        float axn = fmaf(wxn1, x1, fmaf(wxn0, x0, bxn));
        float ahn = bhn;
#pragma unroll
        for (int k = 0; k < 16; ++k) {
            float hk = __shfl_sync(0xFFFFFFFFu, h, sbase + k);
            ar  = fmaf(whr[k], hk, ar);
            az  = fmaf(whz[k], hk, az);
            ahn = fmaf(whn[k], hk, ahn);
        }
        float r = sig_poly(ar);
        float z = sig_poly(az);
        float n = tanh_poly(fmaf(r, ahn, axn));
        h = fmaf(z, h - n, n);
        op[(size_t)t * BATCH * 16] = h;
    }
}

// ---------------------------------------------------------------------------
// MLP
// ---------------------------------------------------------------------------
__global__ void mlp_kernel(const float* __restrict__ W1, const float* __restrict__ b1,
                           const float* __restrict__ W2, const float* __restrict__ b2,
                           float* __restrict__ out) {
    __shared__ float s_w1t[64 * 32];
    __shared__ float s_w2t[32 * 8];
    __shared__ float s_b1[32];
    __shared__ float s_b2[8];
    __shared__ float s_m1[8 * 32];

    const int tid = threadIdx.x;
    for (int idx = tid; idx < 32 * 64; idx += 256) {
        int mm = idx >> 6, k = idx & 63;
        s_w1t[k * 32 + mm] = W1[idx];
    }
    if (tid < 8 * 32) { int o = tid >> 5, k = tid & 31; s_w2t[k * 8 + o] = W2[tid]; }
    if (tid < 32) s_b1[tid] = b1[tid];
    if (tid < 8)  s_b2[tid] = b2[tid];
    __syncthreads();

    const int bl = tid >> 5;
    const int mm = tid & 31;
    const int gb = blockIdx.x * 8 + bl;

    const float* hf = g_h + (size_t)gb * H2;
    const float* hb = g_h + (size_t)(BATCH + gb) * H2;

    float acc = s_b1[mm];
#pragma unroll
    for (int k = 0; k < 64; ++k)
        acc = fmaf(s_w1t[k * 32 + mm], hf[k] + hb[k], acc);
    s_m1[bl * 32 + mm] = acc;
    __syncthreads();

    if (mm < 8) {
        float a2 = s_b2[mm];
#pragma unroll
        for (int k = 0; k < 32; ++k)
            a2 = fmaf(s_w2t[k * 8 + mm], s_m1[bl * 32 + k], a2);
        out[(size_t)gb * 8 + mm] = a2;
    }
}

// ---------------------------------------------------------------------------
// Launch
// ---------------------------------------------------------------------------
extern "C" void kernel_launch(void* const* d_in, const int* in_sizes, int n_in,
                              void* d_out, int out_size) {
    const float* traj   = (const float*)d_in[0];
    const float* w_ih1  = (const float*)d_in[1];
    const float* w_hh1  = (const float*)d_in[2];
    const float* b_ih1  = (const float*)d_in[3];
    const float* b_hh1  = (const float*)d_in[4];
    const float* w_ih2f = (const float*)d_in[5];
    const float* w_hh2f = (const float*)d_in[6];
    const float* b_ih2f = (const float*)d_in[7];
    const float* b_hh2f = (const float*)d_in[8];
    const float* w_ih2b = (const float*)d_in[9];
    const float* w_hh2b = (const float*)d_in[10];
    const float* b_ih2b = (const float*)d_in[11];
    const float* b_hh2b = (const float*)d_in[12];
    const float* W1     = (const float*)d_in[13];
    const float* b1     = (const float*)d_in[14];
    const float* W2     = (const float*)d_in[15];
    const float* b2     = (const float*)d_in[16];

    cudaFuncSetAttribute(gru2_kernel,
                         cudaFuncAttributeMaxDynamicSharedMemorySize, SM2_TOTAL);

    gru1_kernel<<<BATCH / 16, 256>>>(traj, w_ih1, w_hh1, b_ih1, b_hh1);

    dim3 grid2(BATCH / 32, 2);   // (128, 2) = 256 CTAs -> 2 per SM
    gru2_kernel<<<grid2, 128, SM2_TOTAL>>>(w_ih2f, w_hh2f, b_ih2f, b_hh2f,
                                           w_ih2b, w_hh2b, b_ih2b, b_hh2b);

    mlp_kernel<<<BATCH / 8, 256>>>(W1, b1, W2, b2, (float*)d_out);
}

// round 11
// speedup vs baseline: 2.3377x; 1.0564x over previous
#include <cuda_runtime.h>
#include <cuda_fp16.h>
#include <cstdint>

#define TT    256
#define BATCH 4096
#define H1    16
#define H2    64

// ---------------------------------------------------------------------------
// Scratch
// ---------------------------------------------------------------------------
__device__ float g_out1[(size_t)TT * BATCH * H1];   // layer-1 outputs [T][B][16]
__device__ float g_h[2 * (size_t)BATCH * H2];       // final hidden per dir

// ---------------------------------------------------------------------------
// FMA/ALU-only sigmoid core: sig_core(y) = 2^y / (1 + 2^y)
// magic round, deg-5 poly, THREE Newton steps (R10's 2 steps cost 6e-6/gate,
// amplified ~50x by the recurrence -> failed; 3 steps ~4e-11, exact in fp32).
// ---------------------------------------------------------------------------
#define L2E  1.4426950408889634f
#define L2E2 2.8853900817779268f

__device__ __forceinline__ float sig_core(float y) {
    float t = y + 12582912.0f;                       // 1.5*2^23 magic
    int ki = __float_as_int(t) << 23;                // k << 23 (mod 2^32)
    float f = y - (t - 12582912.0f);                 // frac in [-0.5, 0.5]
    float p = 1.33335581e-3f;
    p = fmaf(p, f, 9.61812911e-3f);
    p = fmaf(p, f, 5.55041087e-2f);
    p = fmaf(p, f, 2.40226507e-1f);
    p = fmaf(p, f, 6.93147181e-1f);
    p = fmaf(p, f, 1.0f);
    float v = __int_as_float(__float_as_int(p) + ki);   // 2^y
    float d = 1.0f + v;
    float r = __int_as_float(0x7EF311C3u - (unsigned)__float_as_int(d));
    float s;
    s = fmaf(d, r, -2.0f); r = -r * s;               // Newton 1
    s = fmaf(d, r, -2.0f); r = -r * s;               // Newton 2
    s = fmaf(d, r, -2.0f); r = -r * s;               // Newton 3
    return v * r;
}
__device__ __forceinline__ float tanh_core(float x) {
    return fmaf(2.0f, sig_core(x * L2E2), -1.0f);
}

__device__ __forceinline__ uint32_t smem_u32(const void* p) {
    uint32_t a;
    asm("{ .reg .u64 t; cvta.to.shared.u64 t, %1; cvt.u32.u64 %0, t; }" : "=r"(a) : "l"(p));
    return a;
}

#define LDSM_X4(r0, r1, r2, r3, addr) \
    asm volatile("ldmatrix.sync.aligned.m8n8.x4.shared.b16 {%0,%1,%2,%3}, [%4];" \
        : "=r"(r0), "=r"(r1), "=r"(r2), "=r"(r3) : "r"(addr))

#define MMA_F16(d, a0, a1, a2, a3, bb0, bb1) \
    asm volatile("mma.sync.aligned.m16n8k16.row.col.f32.f16.f16.f32 " \
        "{%0,%1,%2,%3}, {%4,%5,%6,%7}, {%8,%9}, {%0,%1,%2,%3};" \
        : "+f"((d)[0]), "+f"((d)[1]), "+f"((d)[2]), "+f"((d)[3]) \
        : "r"(a0), "r"(a1), "r"(a2), "r"(a3), "r"(bb0), "r"(bb1))

// fp16 split: v = hi + lo (composite product error ~2^-21)
__device__ __forceinline__ void f16_split(float v, unsigned short& hi, unsigned short& lo) {
    __half h = __float2half_rn(v);
    float rem = v - __half2float(h);
    __half l = __float2half_rn(rem);
    hi = __half_as_ushort(h);
    lo = __half_as_ushort(l);
}
__device__ __forceinline__ uint32_t f16_pair(float a, float b, uint32_t& lop) {
    unsigned short ha, la, hb, lb;
    f16_split(a, ha, la);
    f16_split(b, hb, lb);
    lop = (uint32_t)la | ((uint32_t)lb << 16);
    return (uint32_t)ha | ((uint32_t)hb << 16);
}

// ---------------------------------------------------------------------------
// Layer 2 (HMMA, fp16 3-term split): A [32 x 160] double-buffered, B [192 x 160].
//   A: [0:64) h_hi | [64:128) h_lo | [128:144) x_hi | [144:160) x_lo
//   B: [0:64) Whh_hi | [64:128) Whh_lo | [128:144) Wih_hi | [144:160) Wih_lo
// Terms: hi*W_hi + lo*W_hi + hi*W_lo (h and x).  ONE barrier per step.
// M=32/CTA, 4 warps, grid (128,2) -> 2 CTAs/SM.
// ---------------------------------------------------------------------------
#define AROW   336
#define SM_A0  0
#define SM_A1  10752                 // 32*336
#define SM_B   21504
#define SM2_TOTAL (21504 + 192 * 336)    // 86016

__global__ void __launch_bounds__(128, 2)
gru2_kernel(const float* __restrict__ w_ihf, const float* __restrict__ w_hhf,
            const float* __restrict__ b_ihf, const float* __restrict__ b_hhf,
            const float* __restrict__ w_ihb, const float* __restrict__ w_hhb,
            const float* __restrict__ b_ihb, const float* __restrict__ b_hhb) {
    extern __shared__ char sm[];
    const uint32_t smb = smem_u32(sm);
    const int tid = threadIdx.x;
    const int wid = tid >> 5;
    const int lane = tid & 31;
    const int dir = blockIdx.y;
    const int b0 = blockIdx.x * 32;

    const float* w_ih = dir ? w_ihb : w_ihf;
    const float* w_hh = dir ? w_hhb : w_hhf;
    const float* b_ih = dir ? b_ihb : b_ihf;
    const float* b_hh = dir ? b_hhb : b_hhf;

    // ---- build B ----
    for (int idx = tid; idx < 192 * 64; idx += 128) {
        int g = idx >> 6, k = idx & 63;
        unsigned short hi, lo;
        f16_split(w_hh[idx], hi, lo);
        unsigned short* row = (unsigned short*)(sm + SM_B + g * AROW);
        row[k] = hi; row[64 + k] = lo;
    }
    for (int idx = tid; idx < 192 * 16; idx += 128) {
        int g = idx >> 4, k = idx & 15;
        unsigned short hi, lo;
        f16_split(w_ih[idx], hi, lo);
        unsigned short* row = (unsigned short*)(sm + SM_B + g * AROW);
        row[128 + k] = hi; row[144 + k] = lo;
    }
    for (int g = tid; g < 192; g += 128)
        *(uint4*)(sm + SM_B + g * AROW + 320) = make_uint4(0, 0, 0, 0);

    // ---- zero A buf0 (h(0)=0) ----
    for (int idx = tid; idx < 32 * (AROW / 16); idx += 128)
        ((uint4*)(sm + SM_A0))[idx] = make_uint4(0, 0, 0, 0);
    __syncthreads();

    // ---- stage x(t0) ----
    const int xrow = tid >> 2;
    const int xq   = (tid & 3) * 4;
    {
        int t0 = dir ? (TT - 1) : 0;
        float4 xv = *(const float4*)(g_out1 + ((size_t)t0 * BATCH + b0 + xrow) * 16 + xq);
        uint32_t l0, l1;
        uint32_t h0 = f16_pair(xv.x, xv.y, l0);
        uint32_t h1 = f16_pair(xv.z, xv.w, l1);
        char* ar = sm + SM_A0 + xrow * AROW;
        *(uint2*)(ar + 256 + 2 * xq) = make_uint2(h0, h1);
        *(uint2*)(ar + 288 + 2 * xq) = make_uint2(l0, l1);
    }

    // ---- per-warp / per-lane constants ----
    const int mt = wid & 1;
    const int G0 = (wid >> 1) * 32;
    const int lrow = lane & 7;
    const int grp  = lane >> 3;
    const uint32_t aRowOff = (uint32_t)(mt * 16 + lrow + ((grp & 1) << 3)) * AROW
                           + (uint32_t)((grp >> 1) << 4);
    const uint32_t bOff = (uint32_t)(lrow + ((grp >> 1) << 3)) * AROW
                        + (uint32_t)((grp & 1) << 4);
    const uint32_t bBase = smb + SM_B + bOff;

    // biases: r/z pre-scaled by log2(e)
    const int cj = 2 * (lane & 3);
    float2 brL[4], bzL[4], bhn[4], bxn[4];
#pragma unroll
    for (int o = 0; o < 4; ++o) {
        int j = G0 + 8 * o + cj;
        brL[o] = make_float2((b_ih[j] + b_hh[j]) * L2E,
                             (b_ih[j + 1] + b_hh[j + 1]) * L2E);
        bzL[o] = make_float2((b_ih[64 + j] + b_hh[64 + j]) * L2E,
                             (b_ih[65 + j] + b_hh[65 + j]) * L2E);
        bhn[o] = make_float2(b_hh[128 + j], b_hh[129 + j]);
        bxn[o] = make_float2(b_ih[128 + j], b_ih[129 + j]);
    }

    float h[16];
#pragma unroll
    for (int i = 0; i < 16; ++i) h[i] = 0.0f;

    __syncthreads();

    const int row0 = mt * 16 + (lane >> 2);
    const size_t xg_base = (size_t)(b0 + xrow) * 16 + xq;

    for (int step = 0; step < TT; ++step) {
        const uint32_t pa = smb + ((step & 1) ? SM_A1 : SM_A0);
        char* const   pn = sm + ((step & 1) ? SM_A0 : SM_A1);

        // prefetch x(t+1)
        float4 xv;
        const bool do_x = (step + 1 < TT);
        if (do_x) {
            int tn = dir ? (TT - 2 - step) : (step + 1);
            xv = *(const float4*)(g_out1 + (size_t)tn * BATCH * 16 + xg_base);
        }

        // ---- A fragments (10 LDSM) ----
        uint32_t ah[4][4], al[4][4], axh[4], axl[4];
#pragma unroll
        for (int kc = 0; kc < 4; ++kc)
            LDSM_X4(ah[kc][0], ah[kc][1], ah[kc][2], ah[kc][3], pa + aRowOff + kc * 32);
#pragma unroll
        for (int kc = 0; kc < 4; ++kc)
            LDSM_X4(al[kc][0], al[kc][1], al[kc][2], al[kc][3], pa + aRowOff + 128 + kc * 32);
        LDSM_X4(axh[0], axh[1], axh[2], axh[3], pa + aRowOff + 256);
        LDSM_X4(axl[0], axl[1], axl[2], axl[3], pa + aRowOff + 288);

        float d[16][4];
#pragma unroll
        for (int i = 0; i < 16; ++i) {
            d[i][0] = 0.f; d[i][1] = 0.f; d[i][2] = 0.f; d[i][3] = 0.f;
        }

        // ---- MMA phase ----
#pragma unroll
        for (int sec = 0; sec < 3; ++sec) {
#pragma unroll
            for (int nb = 0; nb < 2; ++nb) {
                const uint32_t rowb = bBase + (uint32_t)(sec * 64 + G0 + nb * 16) * AROW;
                const int iH = (sec < 2 ? sec * 4 : 8) + nb * 2;
                const int iX = (sec < 2 ? sec * 4 : 12) + nb * 2;
                uint32_t q0, q1, q2, q3;
#pragma unroll
                for (int kc = 0; kc < 4; ++kc) {
                    LDSM_X4(q0, q1, q2, q3, rowb + kc * 32);
                    MMA_F16(d[iH],     ah[kc][0], ah[kc][1], ah[kc][2], ah[kc][3], q0, q1);
                    MMA_F16(d[iH + 1], ah[kc][0], ah[kc][1], ah[kc][2], ah[kc][3], q2, q3);
                    MMA_F16(d[iH],     al[kc][0], al[kc][1], al[kc][2], al[kc][3], q0, q1);
                    MMA_F16(d[iH + 1], al[kc][0], al[kc][1], al[kc][2], al[kc][3], q2, q3);
                    LDSM_X4(q0, q1, q2, q3, rowb + 128 + kc * 32);
                    MMA_F16(d[iH],     ah[kc][0], ah[kc][1], ah[kc][2], ah[kc][3], q0, q1);
                    MMA_F16(d[iH + 1], ah[kc][0], ah[kc][1], ah[kc][2], ah[kc][3], q2, q3);
                }
                LDSM_X4(q0, q1, q2, q3, rowb + 256);
                MMA_F16(d[iX],     axh[0], axh[1], axh[2], axh[3], q0, q1);
                MMA_F16(d[iX + 1], axh[0], axh[1], axh[2], axh[3], q2, q3);
                MMA_F16(d[iX],     axl[0], axl[1], axl[2], axl[3], q0, q1);
                MMA_F16(d[iX + 1], axl[0], axl[1], axl[2], axl[3], q2, q3);
                LDSM_X4(q0, q1, q2, q3, rowb + 288);
                MMA_F16(d[iX],     axh[0], axh[1], axh[2], axh[3], q0, q1);
                MMA_F16(d[iX + 1], axh[0], axh[1], axh[2], axh[3], q2, q3);
            }
        }

        // No mid-step barrier: epilogue writes pn = pa(step-1); all reads of that
        // buffer completed before step-1's end barrier.

        // ---- epilogue ----
#pragma unroll
        for (int o = 0; o < 4; ++o) {
#pragma unroll
            for (int e = 0; e < 4; ++e) {
                float bRL = (e & 1) ? brL[o].y : brL[o].x;
                float bZL = (e & 1) ? bzL[o].y : bzL[o].x;
                float bH  = (e & 1) ? bhn[o].y : bhn[o].x;
                float bX  = (e & 1) ? bxn[o].y : bxn[o].x;
                float rg = sig_core(fmaf(d[o][e],     L2E, bRL));
                float zg = sig_core(fmaf(d[4 + o][e], L2E, bZL));
                float nn = tanh_core(fmaf(rg, d[8 + o][e] + bH, d[12 + o][e] + bX));
                const int hi = o * 4 + e;
                h[hi] = fmaf(zg, h[hi] - nn, nn);
            }
#pragma unroll
            for (int rsel = 0; rsel < 2; ++rsel) {
                const int e0 = rsel * 2;
                uint32_t LP, HP = f16_pair(h[o * 4 + e0], h[o * 4 + e0 + 1], LP);
                char* ar = pn + (row0 + rsel * 8) * AROW;
                const int j = G0 + 8 * o + cj;
                *(uint32_t*)(ar + 2 * j)       = HP;   // h_hi
                *(uint32_t*)(ar + 128 + 2 * j) = LP;   // h_lo (col 64)
            }
        }

        // stage x(t+1)
        if (do_x) {
            uint32_t l0, l1;
            uint32_t h0 = f16_pair(xv.x, xv.y, l0);
            uint32_t h1 = f16_pair(xv.z, xv.w, l1);
            char* ar = pn + xrow * AROW;
            *(uint2*)(ar + 256 + 2 * xq) = make_uint2(h0, h1);
            *(uint2*)(ar + 288 + 2 * xq) = make_uint2(l0, l1);
        }
        __syncthreads();   // A(next) complete before next step's LDSMs
    }

    // final hidden -> gmem
#pragma unroll
    for (int o = 0; o < 4; ++o) {
#pragma unroll
        for (int rsel = 0; rsel < 2; ++rsel) {
            const int j = G0 + 8 * o + cj;
            float* hp = g_h + ((size_t)dir * BATCH + b0 + row0 + rsel * 8) * H2 + j;
            *(float2*)hp = make_float2(h[o * 4 + rsel * 2], h[o * 4 + rsel * 2 + 1]);
        }
    }
}

// ---------------------------------------------------------------------------
// Layer 1: GRU(2 -> 16), barrier-free warp-shuffle.
// ---------------------------------------------------------------------------
__global__ void __launch_bounds__(256)
gru1_kernel(const float* __restrict__ traj,
            const float* __restrict__ w_ih1,
            const float* __restrict__ w_hh1,
            const float* __restrict__ b_ih1,
            const float* __restrict__ b_hh1) {
    const int tid  = threadIdx.x;
    const int wid  = tid >> 5;
    const int lane = tid & 31;
    const int half = lane >> 4;
    const int j    = lane & 15;
    const int el   = (blockIdx.x * 8 + wid) * 2 + half;

    float whr[16], whz[16], whn[16];
#pragma unroll
    for (int k = 0; k < 16; ++k) {
        whr[k] = w_hh1[(j)      * 16 + k];
        whz[k] = w_hh1[(16 + j) * 16 + k];
        whn[k] = w_hh1[(32 + j) * 16 + k];
    }
    const float wxr0 = w_ih1[j * 2 + 0],        wxr1 = w_ih1[j * 2 + 1];
    const float wxz0 = w_ih1[(16 + j) * 2 + 0], wxz1 = w_ih1[(16 + j) * 2 + 1];
    const float wxn0 = w_ih1[(32 + j) * 2 + 0], wxn1 = w_ih1[(32 + j) * 2 + 1];
    const float br  = b_ih1[j]      + b_hh1[j];
    const float bz  = b_ih1[16 + j] + b_hh1[16 + j];
    const float bxn = b_ih1[32 + j];
    const float bhn = b_hh1[32 + j];

    const float2* xp = (const float2*)(traj + (size_t)el * TT * 2);
    float* op = g_out1 + (size_t)el * 16 + j;
    const int sbase = half << 4;

    float h = 0.0f;
    float2 xv = xp[0];
    for (int t = 0; t < TT; ++t) {
        float x0 = xv.x, x1 = xv.y;
        if (t + 1 < TT) xv = xp[t + 1];

        float ar  = fmaf(wxr1, x1, fmaf(wxr0, x0, br));
        float az  = fmaf(wxz1, x1, fmaf(wxz0, x0, bz));
        float axn = fmaf(wxn1, x1, fmaf(wxn0, x0, bxn));
        float ahn = bhn;
#pragma unroll
        for (int k = 0; k < 16; ++k) {
            float hk = __shfl_sync(0xFFFFFFFFu, h, sbase + k);
            ar  = fmaf(whr[k], hk, ar);
            az  = fmaf(whz[k], hk, az);
            ahn = fmaf(whn[k], hk, ahn);
        }
        float r = sig_core(ar * L2E);
        float z = sig_core(az * L2E);
        float n = tanh_core(fmaf(r, ahn, axn));
        h = fmaf(z, h - n, n);
        op[(size_t)t * BATCH * 16] = h;
    }
}

// ---------------------------------------------------------------------------
// MLP
// ---------------------------------------------------------------------------
__global__ void mlp_kernel(const float* __restrict__ W1, const float* __restrict__ b1,
                           const float* __restrict__ W2, const float* __restrict__ b2,
                           float* __restrict__ out) {
    __shared__ float s_w1t[64 * 32];
    __shared__ float s_w2t[32 * 8];
    __shared__ float s_b1[32];
    __shared__ float s_b2[8];
    __shared__ float s_m1[8 * 32];

    const int tid = threadIdx.x;
    for (int idx = tid; idx < 32 * 64; idx += 256) {
        int mm = idx >> 6, k = idx & 63;
        s_w1t[k * 32 + mm] = W1[idx];
    }
    if (tid < 8 * 32) { int o = tid >> 5, k = tid & 31; s_w2t[k * 8 + o] = W2[tid]; }
    if (tid < 32) s_b1[tid] = b1[tid];
    if (tid < 8)  s_b2[tid] = b2[tid];
    __syncthreads();

    const int bl = tid >> 5;
    const int mm = tid & 31;
    const int gb = blockIdx.x * 8 + bl;

    const float* hf = g_h + (size_t)gb * H2;
    const float* hb = g_h + (size_t)(BATCH + gb) * H2;

    float acc = s_b1[mm];
#pragma unroll
    for (int k = 0; k < 64; ++k)
        acc = fmaf(s_w1t[k * 32 + mm], hf[k] + hb[k], acc);
    s_m1[bl * 32 + mm] = acc;
    __syncthreads();

    if (mm < 8) {
        float a2 = s_b2[mm];
#pragma unroll
        for (int k = 0; k < 32; ++k)
            a2 = fmaf(s_w2t[k * 8 + mm], s_m1[bl * 32 + k], a2);
        out[(size_t)gb * 8 + mm] = a2;
    }
}

// ---------------------------------------------------------------------------
// Launch
// ---------------------------------------------------------------------------
extern "C" void kernel_launch(void* const* d_in, const int* in_sizes, int n_in,
                              void* d_out, int out_size) {
    const float* traj   = (const float*)d_in[0];
    const float* w_ih1  = (const float*)d_in[1];
    const float* w_hh1  = (const float*)d_in[2];
    const float* b_ih1  = (const float*)d_in[3];
    const float* b_hh1  = (const float*)d_in[4];
    const float* w_ih2f = (const float*)d_in[5];
    const float* w_hh2f = (const float*)d_in[6];
    const float* b_ih2f = (const float*)d_in[7];
    const float* b_hh2f = (const float*)d_in[8];
    const float* w_ih2b = (const float*)d_in[9];
    const float* w_hh2b = (const float*)d_in[10];
    const float* b_ih2b = (const float*)d_in[11];
    const float* b_hh2b = (const float*)d_in[12];
    const float* W1     = (const float*)d_in[13];
    const float* b1     = (const float*)d_in[14];
    const float* W2     = (const float*)d_in[15];
    const float* b2     = (const float*)d_in[16];

    cudaFuncSetAttribute(gru2_kernel,
                         cudaFuncAttributeMaxDynamicSharedMemorySize, SM2_TOTAL);

    gru1_kernel<<<BATCH / 16, 256>>>(traj, w_ih1, w_hh1, b_ih1, b_hh1);

    dim3 grid2(BATCH / 32, 2);   // (128, 2) = 256 CTAs -> 2 per SM
    gru2_kernel<<<grid2, 128, SM2_TOTAL>>>(w_ih2f, w_hh2f, b_ih2f, b_hh2f,
                                           w_ih2b, w_hh2b, b_ih2b, b_hh2b);

    mlp_kernel<<<BATCH / 8, 256>>>(W1, b1, W2, b2, (float*)d_out);
}

// round 12
// speedup vs baseline: 2.8943x; 1.2381x over previous
#include <cuda_runtime.h>
#include <cuda_fp16.h>
#include <cstdint>

#define TT    256
#define BATCH 4096
#define H1    16
#define H2    64

// ---------------------------------------------------------------------------
// Scratch
// ---------------------------------------------------------------------------
__device__ float g_out1[(size_t)TT * BATCH * H1];   // layer-1 outputs [T][B][16]
__device__ float g_h[2 * (size_t)BATCH * H2];       // final hidden per dir

// ---------------------------------------------------------------------------
// MUFU activations (EX2+RCP; ~2^-22 rel err -- proven at 2.6e-5 end-to-end in R3).
// Offloads the epilogue from the FMA pipe (which also feeds nothing else) to
// the otherwise-idle MUFU pipe.
// ---------------------------------------------------------------------------
__device__ __forceinline__ float sig_mufu(float x) {
    return __fdividef(1.0f, 1.0f + __expf(-x));
}
__device__ __forceinline__ float tanh_mufu(float x) {
    return fmaf(2.0f, __fdividef(1.0f, 1.0f + __expf(-2.0f * x)), -1.0f);
}

__device__ __forceinline__ uint32_t smem_u32(const void* p) {
    uint32_t a;
    asm("{ .reg .u64 t; cvta.to.shared.u64 t, %1; cvt.u32.u64 %0, t; }" : "=r"(a) : "l"(p));
    return a;
}

#define LDSM_X4(r0, r1, r2, r3, addr) \
    asm volatile("ldmatrix.sync.aligned.m8n8.x4.shared.b16 {%0,%1,%2,%3}, [%4];" \
        : "=r"(r0), "=r"(r1), "=r"(r2), "=r"(r3) : "r"(addr))

#define MMA_F16(d, a0, a1, a2, a3, bb0, bb1) \
    asm volatile("mma.sync.aligned.m16n8k16.row.col.f32.f16.f16.f32 " \
        "{%0,%1,%2,%3}, {%4,%5,%6,%7}, {%8,%9}, {%0,%1,%2,%3};" \
        : "+f"((d)[0]), "+f"((d)[1]), "+f"((d)[2]), "+f"((d)[3]) \
        : "r"(a0), "r"(a1), "r"(a2), "r"(a3), "r"(bb0), "r"(bb1))

// fp16 split: v = hi + lo (composite product error ~2^-21)
__device__ __forceinline__ void f16_split(float v, unsigned short& hi, unsigned short& lo) {
    __half h = __float2half_rn(v);
    float rem = v - __half2float(h);
    __half l = __float2half_rn(rem);
    hi = __half_as_ushort(h);
    lo = __half_as_ushort(l);
}
__device__ __forceinline__ uint32_t f16_pair(float a, float b, uint32_t& lop) {
    unsigned short ha, la, hb, lb;
    f16_split(a, ha, la);
    f16_split(b, hb, lb);
    lop = (uint32_t)la | ((uint32_t)lb << 16);
    return (uint32_t)ha | ((uint32_t)hb << 16);
}

// ---------------------------------------------------------------------------
// Layer 2 (HMMA, fp16 3-term split): A [32 x 160] double-buffered, B [192 x 160].
//   A: [0:64) h_hi | [64:128) h_lo | [128:144) x_hi | [144:160) x_lo
//   B: [0:64) Whh_hi | [64:128) Whh_lo | [128:144) Wih_hi | [144:160) Wih_lo
// Terms: hi*W_hi + lo*W_hi + hi*W_lo (h and x).  ONE barrier per step.
// M=32/CTA, 4 warps, grid (128,2) -> 2 CTAs/SM.
// ---------------------------------------------------------------------------
#define AROW   336
#define SM_A0  0
#define SM_A1  10752                 // 32*336
#define SM_B   21504
#define SM2_TOTAL (21504 + 192 * 336)    // 86016

__global__ void __launch_bounds__(128, 2)
gru2_kernel(const float* __restrict__ w_ihf, const float* __restrict__ w_hhf,
            const float* __restrict__ b_ihf, const float* __restrict__ b_hhf,
            const float* __restrict__ w_ihb, const float* __restrict__ w_hhb,
            const float* __restrict__ b_ihb, const float* __restrict__ b_hhb) {
    extern __shared__ char sm[];
    const uint32_t smb = smem_u32(sm);
    const int tid = threadIdx.x;
    const int wid = tid >> 5;
    const int lane = tid & 31;
    const int dir = blockIdx.y;
    const int b0 = blockIdx.x * 32;

    const float* w_ih = dir ? w_ihb : w_ihf;
    const float* w_hh = dir ? w_hhb : w_hhf;
    const float* b_ih = dir ? b_ihb : b_ihf;
    const float* b_hh = dir ? b_hhb : b_hhf;

    // ---- build B ----
    for (int idx = tid; idx < 192 * 64; idx += 128) {
        int g = idx >> 6, k = idx & 63;
        unsigned short hi, lo;
        f16_split(w_hh[idx], hi, lo);
        unsigned short* row = (unsigned short*)(sm + SM_B + g * AROW);
        row[k] = hi; row[64 + k] = lo;
    }
    for (int idx = tid; idx < 192 * 16; idx += 128) {
        int g = idx >> 4, k = idx & 15;
        unsigned short hi, lo;
        f16_split(w_ih[idx], hi, lo);
        unsigned short* row = (unsigned short*)(sm + SM_B + g * AROW);
        row[128 + k] = hi; row[144 + k] = lo;
    }
    for (int g = tid; g < 192; g += 128)
        *(uint4*)(sm + SM_B + g * AROW + 320) = make_uint4(0, 0, 0, 0);

    // ---- zero A buf0 (h(0)=0) ----
    for (int idx = tid; idx < 32 * (AROW / 16); idx += 128)
        ((uint4*)(sm + SM_A0))[idx] = make_uint4(0, 0, 0, 0);
    __syncthreads();

    // ---- stage x(t0) ----
    const int xrow = tid >> 2;
    const int xq   = (tid & 3) * 4;
    {
        int t0 = dir ? (TT - 1) : 0;
        float4 xv = *(const float4*)(g_out1 + ((size_t)t0 * BATCH + b0 + xrow) * 16 + xq);
        uint32_t l0, l1;
        uint32_t h0 = f16_pair(xv.x, xv.y, l0);
        uint32_t h1 = f16_pair(xv.z, xv.w, l1);
        char* ar = sm + SM_A0 + xrow * AROW;
        *(uint2*)(ar + 256 + 2 * xq) = make_uint2(h0, h1);
        *(uint2*)(ar + 288 + 2 * xq) = make_uint2(l0, l1);
    }

    // ---- per-warp / per-lane constants ----
    const int mt = wid & 1;
    const int G0 = (wid >> 1) * 32;
    const int lrow = lane & 7;
    const int grp  = lane >> 3;
    const uint32_t aRowOff = (uint32_t)(mt * 16 + lrow + ((grp & 1) << 3)) * AROW
                           + (uint32_t)((grp >> 1) << 4);
    const uint32_t bOff = (uint32_t)(lrow + ((grp >> 1) << 3)) * AROW
                        + (uint32_t)((grp & 1) << 4);
    const uint32_t bBase = smb + SM_B + bOff;

    // biases -> registers
    const int cj = 2 * (lane & 3);
    float2 br[4], bz[4], bhn[4], bxn[4];
#pragma unroll
    for (int o = 0; o < 4; ++o) {
        int j = G0 + 8 * o + cj;
        br[o]  = make_float2(b_ih[j] + b_hh[j],           b_ih[j + 1] + b_hh[j + 1]);
        bz[o]  = make_float2(b_ih[64 + j] + b_hh[64 + j], b_ih[65 + j] + b_hh[65 + j]);
        bhn[o] = make_float2(b_hh[128 + j], b_hh[129 + j]);
        bxn[o] = make_float2(b_ih[128 + j], b_ih[129 + j]);
    }

    float h[16];
#pragma unroll
    for (int i = 0; i < 16; ++i) h[i] = 0.0f;

    __syncthreads();

    const int row0 = mt * 16 + (lane >> 2);
    const size_t xg_base = (size_t)(b0 + xrow) * 16 + xq;

    for (int step = 0; step < TT; ++step) {
        const uint32_t pa = smb + ((step & 1) ? SM_A1 : SM_A0);
        char* const   pn = sm + ((step & 1) ? SM_A0 : SM_A1);

        // prefetch x(t+1)
        float4 xv;
        const bool do_x = (step + 1 < TT);
        if (do_x) {
            int tn = dir ? (TT - 2 - step) : (step + 1);
            xv = *(const float4*)(g_out1 + (size_t)tn * BATCH * 16 + xg_base);
        }

        // ---- A fragments (10 LDSM) ----
        uint32_t ah[4][4], al[4][4], axh[4], axl[4];
#pragma unroll
        for (int kc = 0; kc < 4; ++kc)
            LDSM_X4(ah[kc][0], ah[kc][1], ah[kc][2], ah[kc][3], pa + aRowOff + kc * 32);
#pragma unroll
        for (int kc = 0; kc < 4; ++kc)
            LDSM_X4(al[kc][0], al[kc][1], al[kc][2], al[kc][3], pa + aRowOff + 128 + kc * 32);
        LDSM_X4(axh[0], axh[1], axh[2], axh[3], pa + aRowOff + 256);
        LDSM_X4(axl[0], axl[1], axl[2], axl[3], pa + aRowOff + 288);

        float d[16][4];
#pragma unroll
        for (int i = 0; i < 16; ++i) {
            d[i][0] = 0.f; d[i][1] = 0.f; d[i][2] = 0.f; d[i][3] = 0.f;
        }

        // ---- MMA phase ----
#pragma unroll
        for (int sec = 0; sec < 3; ++sec) {
#pragma unroll
            for (int nb = 0; nb < 2; ++nb) {
                const uint32_t rowb = bBase + (uint32_t)(sec * 64 + G0 + nb * 16) * AROW;
                const int iH = (sec < 2 ? sec * 4 : 8) + nb * 2;
                const int iX = (sec < 2 ? sec * 4 : 12) + nb * 2;
                uint32_t q0, q1, q2, q3;
#pragma unroll
                for (int kc = 0; kc < 4; ++kc) {
                    LDSM_X4(q0, q1, q2, q3, rowb + kc * 32);
                    MMA_F16(d[iH],     ah[kc][0], ah[kc][1], ah[kc][2], ah[kc][3], q0, q1);
                    MMA_F16(d[iH + 1], ah[kc][0], ah[kc][1], ah[kc][2], ah[kc][3], q2, q3);
                    MMA_F16(d[iH],     al[kc][0], al[kc][1], al[kc][2], al[kc][3], q0, q1);
                    MMA_F16(d[iH + 1], al[kc][0], al[kc][1], al[kc][2], al[kc][3], q2, q3);
                    LDSM_X4(q0, q1, q2, q3, rowb + 128 + kc * 32);
                    MMA_F16(d[iH],     ah[kc][0], ah[kc][1], ah[kc][2], ah[kc][3], q0, q1);
                    MMA_F16(d[iH + 1], ah[kc][0], ah[kc][1], ah[kc][2], ah[kc][3], q2, q3);
                }
                LDSM_X4(q0, q1, q2, q3, rowb + 256);
                MMA_F16(d[iX],     axh[0], axh[1], axh[2], axh[3], q0, q1);
                MMA_F16(d[iX + 1], axh[0], axh[1], axh[2], axh[3], q2, q3);
                MMA_F16(d[iX],     axl[0], axl[1], axl[2], axl[3], q0, q1);
                MMA_F16(d[iX + 1], axl[0], axl[1], axl[2], axl[3], q2, q3);
                LDSM_X4(q0, q1, q2, q3, rowb + 288);
                MMA_F16(d[iX],     axh[0], axh[1], axh[2], axh[3], q0, q1);
                MMA_F16(d[iX + 1], axh[0], axh[1], axh[2], axh[3], q2, q3);
            }
        }

        // No mid-step barrier: epilogue writes pn = pa(step-1); all reads of that
        // buffer completed before step-1's end barrier.

        // ---- epilogue (MUFU pipe) ----
#pragma unroll
        for (int o = 0; o < 4; ++o) {
#pragma unroll
            for (int e = 0; e < 4; ++e) {
                float bR = (e & 1) ? br[o].y : br[o].x;
                float bZ = (e & 1) ? bz[o].y : bz[o].x;
                float bH = (e & 1) ? bhn[o].y : bhn[o].x;
                float bX = (e & 1) ? bxn[o].y : bxn[o].x;
                float rg = sig_mufu(d[o][e] + bR);
                float zg = sig_mufu(d[4 + o][e] + bZ);
                float nn = tanh_mufu(fmaf(rg, d[8 + o][e] + bH, d[12 + o][e] + bX));
                const int hi = o * 4 + e;
                h[hi] = fmaf(zg, h[hi] - nn, nn);
            }
#pragma unroll
            for (int rsel = 0; rsel < 2; ++rsel) {
                const int e0 = rsel * 2;
                uint32_t LP, HP = f16_pair(h[o * 4 + e0], h[o * 4 + e0 + 1], LP);
                char* ar = pn + (row0 + rsel * 8) * AROW;
                const int j = G0 + 8 * o + cj;
                *(uint32_t*)(ar + 2 * j)       = HP;   // h_hi
                *(uint32_t*)(ar + 128 + 2 * j) = LP;   // h_lo (col 64)
            }
        }

        // stage x(t+1)
        if (do_x) {
            uint32_t l0, l1;
            uint32_t h0 = f16_pair(xv.x, xv.y, l0);
            uint32_t h1 = f16_pair(xv.z, xv.w, l1);
            char* ar = pn + xrow * AROW;
            *(uint2*)(ar + 256 + 2 * xq) = make_uint2(h0, h1);
            *(uint2*)(ar + 288 + 2 * xq) = make_uint2(l0, l1);
        }
        __syncthreads();   // A(next) complete before next step's LDSMs
    }

    // final hidden -> gmem
#pragma unroll
    for (int o = 0; o < 4; ++o) {
#pragma unroll
        for (int rsel = 0; rsel < 2; ++rsel) {
            const int j = G0 + 8 * o + cj;
            float* hp = g_h + ((size_t)dir * BATCH + b0 + row0 + rsel * 8) * H2 + j;
            *(float2*)hp = make_float2(h[o * 4 + rsel * 2], h[o * 4 + rsel * 2 + 1]);
        }
    }
}

// ---------------------------------------------------------------------------
// Layer 1: GRU(2 -> 16), barrier-free warp-shuffle, MUFU activations.
// ---------------------------------------------------------------------------
__global__ void __launch_bounds__(256)
gru1_kernel(const float* __restrict__ traj,
            const float* __restrict__ w_ih1,
            const float* __restrict__ w_hh1,
            const float* __restrict__ b_ih1,
            const float* __restrict__ b_hh1) {
    const int tid  = threadIdx.x;
    const int wid  = tid >> 5;
    const int lane = tid & 31;
    const int half = lane >> 4;
    const int j    = lane & 15;
    const int el   = (blockIdx.x * 8 + wid) * 2 + half;

    float whr[16], whz[16], whn[16];
#pragma unroll
    for (int k = 0; k < 16; ++k) {
        whr[k] = w_hh1[(j)      * 16 + k];
        whz[k] = w_hh1[(16 + j) * 16 + k];
        whn[k] = w_hh1[(32 + j) * 16 + k];
    }
    const float wxr0 = w_ih1[j * 2 + 0],        wxr1 = w_ih1[j * 2 + 1];
    const float wxz0 = w_ih1[(16 + j) * 2 + 0], wxz1 = w_ih1[(16 + j) * 2 + 1];
    const float wxn0 = w_ih1[(32 + j) * 2 + 0], wxn1 = w_ih1[(32 + j) * 2 + 1];
    const float br  = b_ih1[j]      + b_hh1[j];
    const float bz  = b_ih1[16 + j] + b_hh1[16 + j];
    const float bxn = b_ih1[32 + j];
    const float bhn = b_hh1[32 + j];

    const float2* xp = (const float2*)(traj + (size_t)el * TT * 2);
    float* op = g_out1 + (size_t)el * 16 + j;
    const int sbase = half << 4;

    float h = 0.0f;
    float2 xv = xp[0];
    for (int t = 0; t < TT; ++t) {
        float x0 = xv.x, x1 = xv.y;
        if (t + 1 < TT) xv = xp[t + 1];

        float ar  = fmaf(wxr1, x1, fmaf(wxr0, x0, br));
        float az  = fmaf(wxz1, x1, fmaf(wxz0, x0, bz));
        float axn = fmaf(wxn1, x1, fmaf(wxn0, x0, bxn));
        float ahn = bhn;
#pragma unroll
        for (int k = 0; k < 16; ++k) {
            float hk = __shfl_sync(0xFFFFFFFFu, h, sbase + k);
            ar  = fmaf(whr[k], hk, ar);
            az  = fmaf(whz[k], hk, az);
            ahn = fmaf(whn[k], hk, ahn);
        }
        float r = sig_mufu(ar);
        float z = sig_mufu(az);
        float n = tanh_mufu(fmaf(r, ahn, axn));
        h = fmaf(z, h - n, n);
        op[(size_t)t * BATCH * 16] = h;
    }
}

// ---------------------------------------------------------------------------
// MLP
// ---------------------------------------------------------------------------
__global__ void mlp_kernel(const float* __restrict__ W1, const float* __restrict__ b1,
                           const float* __restrict__ W2, const float* __restrict__ b2,
                           float* __restrict__ out) {
    __shared__ float s_w1t[64 * 32];
    __shared__ float s_w2t[32 * 8];
    __shared__ float s_b1[32];
    __shared__ float s_b2[8];
    __shared__ float s_m1[8 * 32];

    const int tid = threadIdx.x;
    for (int idx = tid; idx < 32 * 64; idx += 256) {
        int mm = idx >> 6, k = idx & 63;
        s_w1t[k * 32 + mm] = W1[idx];
    }
    if (tid < 8 * 32) { int o = tid >> 5, k = tid & 31; s_w2t[k * 8 + o] = W2[tid]; }
    if (tid < 32) s_b1[tid] = b1[tid];
    if (tid < 8)  s_b2[tid] = b2[tid];
    __syncthreads();

    const int bl = tid >> 5;
    const int mm = tid & 31;
    const int gb = blockIdx.x * 8 + bl;

    const float* hf = g_h + (size_t)gb * H2;
    const float* hb = g_h + (size_t)(BATCH + gb) * H2;

    float acc = s_b1[mm];
#pragma unroll
    for (int k = 0; k < 64; ++k)
        acc = fmaf(s_w1t[k * 32 + mm], hf[k] + hb[k], acc);
    s_m1[bl * 32 + mm] = acc;
    __syncthreads();

    if (mm < 8) {
        float a2 = s_b2[mm];
#pragma unroll
        for (int k = 0; k < 32; ++k)
            a2 = fmaf(s_w2t[k * 8 + mm], s_m1[bl * 32 + k], a2);
        out[(size_t)gb * 8 + mm] = a2;
    }
}

// ---------------------------------------------------------------------------
// Launch
// ---------------------------------------------------------------------------
extern "C" void kernel_launch(void* const* d_in, const int* in_sizes, int n_in,
                              void* d_out, int out_size) {
    const float* traj   = (const float*)d_in[0];
    const float* w_ih1  = (const float*)d_in[1];
    const float* w_hh1  = (const float*)d_in[2];
    const float* b_ih1  = (const float*)d_in[3];
    const float* b_hh1  = (const float*)d_in[4];
    const float* w_ih2f = (const float*)d_in[5];
    const float* w_hh2f = (const float*)d_in[6];
    const float* b_ih2f = (const float*)d_in[7];
    const float* b_hh2f = (const float*)d_in[8];
    const float* w_ih2b = (const float*)d_in[9];
    const float* w_hh2b = (const float*)d_in[10];
    const float* b_ih2b = (const float*)d_in[11];
    const float* b_hh2b = (const float*)d_in[12];
    const float* W1     = (const float*)d_in[13];
    const float* b1     = (const float*)d_in[14];
    const float* W2     = (const float*)d_in[15];
    const float* b2     = (const float*)d_in[16];

    cudaFuncSetAttribute(gru2_kernel,
                         cudaFuncAttributeMaxDynamicSharedMemorySize, SM2_TOTAL);

    gru1_kernel<<<BATCH / 16, 256>>>(traj, w_ih1, w_hh1, b_ih1, b_hh1);

    dim3 grid2(BATCH / 32, 2);   // (128, 2) = 256 CTAs -> 2 per SM
    gru2_kernel<<<grid2, 128, SM2_TOTAL>>>(w_ih2f, w_hh2f, b_ih2f, b_hh2f,
                                           w_ih2b, w_hh2b, b_ih2b, b_hh2b);

    mlp_kernel<<<BATCH / 8, 256>>>(W1, b1, W2, b2, (float*)d_out);
}